// round 11
// baseline (speedup 1.0000x reference)
#include <cuda_runtime.h>
#include <cuda_bf16.h>
#include <cstdint>
#include <math.h>

#define NN 10000
#define DD 128
#define KSEL 5000
#define BM 64
#define BK 32
#define NST 313                 // ceil(10000/32) k-stages
#define NKPAD (NST * BK)        // 10016 padded k rows
#define JW 10048                // padded j width (157*64)
#define NSPLIT 12
#define NJT 157                 // j tiles of 64
#define CI 2048                 // gather chunk

// d_out layout (float32): x_pool[5000*128] | adj_pool[5000*5000] | motif_pool[5000*5000] | scores[10000] | top_idx[5000]
#define XP_OFF   0LL
#define ADJ_OFF  640000LL
#define MOT_OFF  (640000LL + 25000000LL)
#define SC_OFF   (640000LL + 50000000LL)
#define IDX_OFF  (SC_OFF + 10000LL)

// ---------------- scratch (device globals; zero-initialized at load; pads never written) ----------------
__device__ __nv_bfloat16 g_Mbh[(size_t)NKPAD * JW];   // motif bf16 hi, [i][j]
__device__ __nv_bfloat16 g_Mbl[(size_t)NKPAD * JW];   // motif bf16 lo
__device__ float g_colpart[8][NN];
__device__ float g_dinv[NN];
__device__ float g_P[(size_t)NN * DD];                 // dinv_i * (x @ W^T), fp32
__device__ __nv_bfloat16 g_Pbh[(size_t)NKPAD * DD];    // P bf16 hi, [i][d]
__device__ __nv_bfloat16 g_Pbl[(size_t)NKPAD * DD];    // P bf16 lo
__device__ float g_Gpart[NSPLIT][(size_t)NN * DD];     // split-K partials
__device__ float g_h[(size_t)NN * DD];
__device__ float g_scores[NN];
__device__ int   g_sel[NN];
__device__ int   g_epos[NN];                           // exclusive scan of g_sel
__device__ int   g_idx[KSEL];

// ---------------- PTX helpers (sm_80-level; compile on compute_103 family target) ----------------
__device__ __forceinline__ uint32_t smem_u32(const void* p) {
    uint32_t a;
    asm("{ .reg .u64 t; cvta.to.shared.u64 t, %1; cvt.u32.u64 %0, t; }" : "=r"(a) : "l"(p));
    return a;
}
__device__ __forceinline__ void cpasync16(uint32_t dst, const void* src) {
    asm volatile("cp.async.cg.shared.global [%0], [%1], 16;" :: "r"(dst), "l"(src));
}
#define CP_COMMIT() asm volatile("cp.async.commit_group;" ::: "memory")
#define CP_WAIT(n)  asm volatile("cp.async.wait_group %0;" :: "n"(n) : "memory")

__device__ __forceinline__ void ldsm4t(uint32_t* r, uint32_t addr) {
    asm volatile("ldmatrix.sync.aligned.m8n8.x4.trans.shared.b16 {%0,%1,%2,%3}, [%4];"
        : "=r"(r[0]), "=r"(r[1]), "=r"(r[2]), "=r"(r[3]) : "r"(addr));
}
__device__ __forceinline__ void mma16816(float* c, const uint32_t* a, const uint32_t* b) {
    asm volatile("mma.sync.aligned.m16n8k16.row.col.f32.bf16.bf16.f32 "
        "{%0,%1,%2,%3}, {%4,%5,%6,%7}, {%8,%9}, {%0,%1,%2,%3};"
        : "+f"(c[0]), "+f"(c[1]), "+f"(c[2]), "+f"(c[3])
        : "r"(a[0]), "r"(a[1]), "r"(a[2]), "r"(a[3]), "r"(b[0]), "r"(b[1]));
}

// ---------------- 1) prep: motif -> bf16 hi/lo [i][j] (padded) + column partial sums ----------------
__global__ __launch_bounds__(256) void prep_kernel(const float* __restrict__ motif) {
    int part = blockIdx.y;                      // 8 i-parts of 1250 rows
    int jg = blockIdx.x * 256 + threadIdx.x;    // group of 4 j's
    int j = jg * 4;
    if (j >= NN) return;
    int r0 = part * (NN / 8), r1 = r0 + (NN / 8);
    float s0 = 0.f, s1 = 0.f, s2 = 0.f, s3 = 0.f;
    for (int i = r0; i < r1; i++) {
        float4 v = *(const float4*)&motif[(size_t)i * NN + j];
        s0 += v.x; s1 += v.y; s2 += v.z; s3 += v.w;
        __nv_bfloat162 h01 = __floats2bfloat162_rn(v.x, v.y);
        __nv_bfloat162 h23 = __floats2bfloat162_rn(v.z, v.w);
        __nv_bfloat162 l01 = __floats2bfloat162_rn(v.x - __bfloat162float(h01.x),
                                                   v.y - __bfloat162float(h01.y));
        __nv_bfloat162 l23 = __floats2bfloat162_rn(v.z - __bfloat162float(h23.x),
                                                   v.w - __bfloat162float(h23.y));
        uint2 hw, lw;
        hw.x = *(uint32_t*)&h01; hw.y = *(uint32_t*)&h23;
        lw.x = *(uint32_t*)&l01; lw.y = *(uint32_t*)&l23;
        *(uint2*)&g_Mbh[(size_t)i * JW + j] = hw;
        *(uint2*)&g_Mbl[(size_t)i * JW + j] = lw;
    }
    *(float4*)&g_colpart[part][j] = make_float4(s0, s1, s2, s3);
}

// ---------------- 2) deg -> dinv ----------------
__global__ __launch_bounds__(256) void dinv_kernel() {
    int j = blockIdx.x * 256 + threadIdx.x;
    if (j >= NN) return;
    float d = 1.0f;  // +I diagonal
    #pragma unroll
    for (int p = 0; p < 8; p++) d += g_colpart[p][j];
    g_dinv[j] = 1.0f / sqrtf(d);
}

// ---------------- 3) P[i,d] = dinv[i]*(x@W^T); also emit bf16 hi/lo in [i][d] ----------------
__global__ __launch_bounds__(128) void compute_P_kernel(const float* __restrict__ x,
                                                        const float* __restrict__ W) {
    __shared__ float smX[16][128];
    int tid = threadIdx.x;   // = d
    int i0 = blockIdx.x * 16;
    for (int f = tid; f < 16 * 32; f += 128) {
        int r = f >> 5, c = (f & 31) * 4;
        *(float4*)&smX[r][c] = *(const float4*)&x[(size_t)(i0 + r) * DD + c];
    }
    __syncthreads();
    float acc[16];
    #pragma unroll
    for (int r = 0; r < 16; r++) acc[r] = 0.f;
    const float* wrow = W + (size_t)tid * DD;
    for (int e = 0; e < DD; e += 4) {
        float4 w4 = *(const float4*)&wrow[e];
        #pragma unroll
        for (int r = 0; r < 16; r++) {
            float4 x4 = *(const float4*)&smX[r][e];
            acc[r] += x4.x * w4.x + x4.y * w4.y + x4.z * w4.z + x4.w * w4.w;
        }
    }
    #pragma unroll
    for (int r = 0; r < 16; r++) {
        int gi = i0 + r;
        float p = g_dinv[gi] * acc[r];
        g_P[(size_t)gi * DD + tid] = p;
        __nv_bfloat16 hb = __float2bfloat16(p);
        g_Pbh[(size_t)gi * DD + tid] = hb;
        g_Pbl[(size_t)gi * DD + tid] = __float2bfloat16(p - __bfloat162float(hb));
    }
}

// ---------------- 4) HMMA GEMM: G[j,d] = sum_i motif[i,j]*P[i,d], bf16 hi/lo x3 ----------------
// Both operands pre-split bf16 in K-major global memory (zero-padded) -> pure cp.async staging.
__global__ __launch_bounds__(256) void hmma_gemm_kernel() {
    extern __shared__ __align__(128) char dynsm[];
    const uint32_t smbase = smem_u32(dynsm);
    const uint32_t A_h = smbase;             // [2][32][64] bf16 : 2 x 4096B
    const uint32_t A_l = smbase + 8192;
    const uint32_t B_h = smbase + 16384;     // [2][32][128] bf16: 2 x 8192B
    const uint32_t B_l = smbase + 32768;     // total 49152B

    const int tid = threadIdx.x;
    const int lane = tid & 31;
    const int wid = tid >> 5;
    const int wm = wid & 1;      // 2 warp-rows (m)
    const int wn = wid >> 1;     // 4 warp-cols (n)
    const int j0 = blockIdx.x * BM;
    const int split = blockIdx.y;
    const int sbeg = (split == 0) ? 0 : (26 * split + 1);   // split0: 27 stages, rest 26
    const int ns = (split == 0) ? 27 : 26;

    // A loader: thread -> (k row ak, 16B j-chunk aj)
    const int ak = tid >> 3;
    const int aj = tid & 7;
    const uint32_t aOff = (uint32_t)ak * 128 + (uint32_t)(aj ^ (ak & 7)) * 16;
    const __nv_bfloat16* aSrcH = g_Mbh + (size_t)ak * JW + j0 + aj * 8;
    const __nv_bfloat16* aSrcL = g_Mbl + (size_t)ak * JW + j0 + aj * 8;

    // B loader: thread -> (k row bk, chunks bc and bc+8)
    const int bk = tid >> 3;
    const int bc = tid & 7;
    const uint32_t bOff0 = (uint32_t)bk * 256 + (uint32_t)(bc ^ (bk & 7)) * 16;
    const uint32_t bOff1 = bOff0 + 128;
    const __nv_bfloat16* bSrcH = g_Pbh + (size_t)bk * DD + bc * 8;
    const __nv_bfloat16* bSrcL = g_Pbl + (size_t)bk * DD + bc * 8;

    float acc[2][4][4];
    #pragma unroll
    for (int mt = 0; mt < 2; mt++)
        #pragma unroll
        for (int nt = 0; nt < 4; nt++)
            #pragma unroll
            for (int q = 0; q < 4; q++) acc[mt][nt][q] = 0.f;

#define CP_STAGE(t) do { \
    size_t _k = (size_t)(sbeg + (t)) * BK; \
    uint32_t _ab = ((t) & 1) * 4096u, _bb = ((t) & 1) * 8192u; \
    cpasync16(A_h + _ab + aOff, aSrcH + _k * JW); \
    cpasync16(A_l + _ab + aOff, aSrcL + _k * JW); \
    cpasync16(B_h + _bb + bOff0, bSrcH + _k * DD); \
    cpasync16(B_h + _bb + bOff1, bSrcH + _k * DD + 64); \
    cpasync16(B_l + _bb + bOff0, bSrcL + _k * DD); \
    cpasync16(B_l + _bb + bOff1, bSrcL + _k * DD + 64); \
    CP_COMMIT(); \
} while (0)

    CP_STAGE(0);
    CP_STAGE(1);

    for (int t = 0; t < ns; t++) {
        const int b = t & 1;
        if (t + 1 < ns) { CP_WAIT(1); } else { CP_WAIT(0); }
        __syncthreads();

        const uint32_t Ah = A_h + b * 4096u, Al = A_l + b * 4096u;
        const uint32_t Bh = B_h + b * 8192u, Bl = B_l + b * 8192u;
        #pragma unroll
        for (int kb = 0; kb < 2; kb++) {
            uint32_t ah[2][4], al[2][4], bh[2][4], bl[2][4];
            const int krA = kb * 16 + (lane & 7) + ((lane & 16) ? 8 : 0);
            #pragma unroll
            for (int mt = 0; mt < 2; mt++) {
                uint32_t ch = (uint32_t)((wm * 4 + mt * 2 + ((lane & 8) ? 1 : 0)) ^ (krA & 7));
                uint32_t ad = (uint32_t)krA * 128 + ch * 16;
                ldsm4t(ah[mt], Ah + ad);
                ldsm4t(al[mt], Al + ad);
            }
            const int krB = kb * 16 + (lane & 7) + ((lane & 8) ? 8 : 0);
            #pragma unroll
            for (int np = 0; np < 2; np++) {
                uint32_t c = (uint32_t)(wn * 4 + np * 2 + ((lane & 16) ? 1 : 0));
                uint32_t csw = (c & 8u) | ((c ^ (uint32_t)krB) & 7u);
                uint32_t bd = (uint32_t)krB * 256 + csw * 16;
                ldsm4t(bh[np], Bh + bd);
                ldsm4t(bl[np], Bl + bd);
            }
            #pragma unroll
            for (int mt = 0; mt < 2; mt++)
                #pragma unroll
                for (int nt = 0; nt < 4; nt++) {
                    const int np = nt >> 1, hf = nt & 1;
                    uint32_t bhp[2] = {bh[np][hf * 2], bh[np][hf * 2 + 1]};
                    uint32_t blp[2] = {bl[np][hf * 2], bl[np][hf * 2 + 1]};
                    mma16816(acc[mt][nt], ah[mt], bhp);   // hi*hi
                    mma16816(acc[mt][nt], ah[mt], blp);   // hi*lo
                    mma16816(acc[mt][nt], al[mt], bhp);   // lo*hi
                }
        }
        __syncthreads();
        if (t + 2 < ns) CP_STAGE(t + 2);
    }
#undef CP_STAGE

    // store partial G
    float* G = g_Gpart[split];
    #pragma unroll
    for (int mt = 0; mt < 2; mt++)
        #pragma unroll
        for (int nt = 0; nt < 4; nt++) {
            int j = j0 + wm * 32 + mt * 16 + (lane >> 2);
            int d = wn * 32 + nt * 8 + (lane & 3) * 2;
            if (j < NN) {
                float2 v = make_float2(acc[mt][nt][0], acc[mt][nt][1]);
                *(float2*)(G + (size_t)j * DD + d) = v;
            }
            if (j + 8 < NN) {
                float2 v = make_float2(acc[mt][nt][2], acc[mt][nt][3]);
                *(float2*)(G + (size_t)(j + 8) * DD + d) = v;
            }
        }
}

// ---------------- 5) h = tanh(dinv_j*(sum G + P_j) + b); scores ----------------
__global__ __launch_bounds__(128) void epilogue_kernel(const float* __restrict__ b_gcn,
                                                       const float* __restrict__ w_score,
                                                       const float* __restrict__ b_score,
                                                       float* __restrict__ out) {
    int j = blockIdx.x;
    int d = threadIdx.x;
    size_t o = (size_t)j * DD + d;
    float g = g_P[o];
    #pragma unroll
    for (int s = 0; s < NSPLIT; s++) g += g_Gpart[s][o];
    float hv = tanhf(g_dinv[j] * g + b_gcn[d]);
    g_h[o] = hv;
    float v = hv * w_score[d];
    #pragma unroll
    for (int off = 16; off > 0; off >>= 1) v += __shfl_down_sync(0xffffffffu, v, off);
    __shared__ float ws[4];
    if ((d & 31) == 0) ws[d >> 5] = v;
    __syncthreads();
    if (d == 0) {
        float sc = ((ws[0] + ws[1]) + (ws[2] + ws[3])) + b_score[0];
        g_scores[j] = sc;
        out[SC_OFF + j] = sc;
    }
}

// ---------------- 6) top-k via exact rank (matches lax.top_k stable ties) ----------------
__global__ __launch_bounds__(256) void topk_rank_kernel() {
    __shared__ float ss[NN];
    int tid = threadIdx.x;
    for (int f = tid; f < NN; f += 256) ss[f] = g_scores[f];
    __syncthreads();
    int j = blockIdx.x * 256 + tid;
    if (j >= NN) return;
    float sj = ss[j];
    int rank = 0;
    for (int i = 0; i < NN; i++) {
        float si = ss[i];
        rank += (si > sj) ? 1 : ((si == sj && i < j) ? 1 : 0);
    }
    g_sel[j] = (rank < KSEL) ? 1 : 0;
}

// ---------------- 7) compact selected indices (ascending) + exclusive scan ----------------
__global__ __launch_bounds__(256) void compact_kernel(float* __restrict__ out) {
    __shared__ int wsum[8];
    __shared__ int carry;
    int tid = threadIdx.x, lane = tid & 31, wid = tid >> 5;
    if (tid == 0) carry = 0;
    __syncthreads();
    for (int base = 0; base < NN; base += 256) {
        int j = base + tid;
        int f = (j < NN) ? g_sel[j] : 0;
        int xv = f;
        #pragma unroll
        for (int o = 1; o < 32; o <<= 1) {
            int y = __shfl_up_sync(0xffffffffu, xv, o);
            if (lane >= o) xv += y;
        }
        if (lane == 31) wsum[wid] = xv;
        __syncthreads();
        int woff = 0;
        #pragma unroll
        for (int w = 0; w < 8; w++) if (w < wid) woff += wsum[w];
        int incl = xv + woff;
        int pos = carry + incl - f;
        if (j < NN) {
            g_epos[j] = pos;
            if (f) {
                g_idx[pos] = j;
                out[IDX_OFF + pos] = (float)j;
            }
        }
        __syncthreads();
        if (tid == 255) carry += incl;
        __syncthreads();
    }
}

// ---------------- 8) x_pool gather ----------------
__global__ __launch_bounds__(128) void gather_x_kernel(float* __restrict__ out) {
    int r = blockIdx.x;
    int d = threadIdx.x;
    int ir = g_idx[r];
    out[XP_OFF + (size_t)r * DD + d] = g_h[(size_t)ir * DD + d];
}

// ---------------- 9) adjacency/motif pool gathers (smem-staged, coalesced DRAM reads) ----------------
__global__ __launch_bounds__(256) void gather_pools_kernel(const float* __restrict__ adj,
                                                           const float* __restrict__ motif,
                                                           float* __restrict__ out) {
    __shared__ float smA[CI];
    __shared__ float smM[CI];
    __shared__ int scr[2];
    int tid = threadIdx.x;
    int r = blockIdx.x;
    int ir = g_idx[r];
    const float* arow = adj   + (size_t)ir * NN;
    const float* mrow = motif + (size_t)ir * NN;
    float* oa = out + ADJ_OFF + (size_t)r * KSEL;
    float* om = out + MOT_OFF + (size_t)r * KSEL;

    for (int q0 = 0; q0 < NN; q0 += CI) {
        int qn = min(CI, NN - q0);
        for (int f = tid * 4; f < qn; f += 1024) {
            *(float4*)&smA[f] = *(const float4*)&arow[q0 + f];
            *(float4*)&smM[f] = *(const float4*)&mrow[q0 + f];
        }
        if (tid == 0) {
            scr[0] = g_epos[q0];
            scr[1] = (q0 + CI < NN) ? g_epos[q0 + CI] : KSEL;
        }
        __syncthreads();
        int c0 = scr[0], c1 = scr[1];
        for (int c = c0 + tid; c < c1; c += 256) {
            int ic = g_idx[c] - q0;
            oa[c] = smA[ic];
            om[c] = smM[ic];
        }
        __syncthreads();
    }
}

// ---------------- launch ----------------
extern "C" void kernel_launch(void* const* d_in, const int* in_sizes, int n_in,
                              void* d_out, int out_size) {
    const float* x       = (const float*)d_in[0];
    const float* adj     = (const float*)d_in[1];
    const float* motif   = (const float*)d_in[2];
    const float* W       = (const float*)d_in[3];
    const float* b_gcn   = (const float*)d_in[4];
    const float* w_score = (const float*)d_in[5];
    const float* b_score = (const float*)d_in[6];
    float* out = (float*)d_out;

    prep_kernel<<<dim3(10, 8), 256>>>(motif);
    dinv_kernel<<<(NN + 255) / 256, 256>>>();
    compute_P_kernel<<<NN / 16, 128>>>(x, W);
    hmma_gemm_kernel<<<dim3(NJT, NSPLIT), 256, 49152>>>();
    epilogue_kernel<<<NN, 128>>>(b_gcn, w_score, b_score, out);
    topk_rank_kernel<<<(NN + 255) / 256, 256>>>();
    compact_kernel<<<1, 256>>>(out);
    gather_x_kernel<<<KSEL, 128>>>(out);
    gather_pools_kernel<<<KSEL, 256>>>(adj, motif, out);
}

// round 12
// speedup vs baseline: 1.3275x; 1.3275x over previous
#include <cuda_runtime.h>
#include <cuda_bf16.h>
#include <cstdint>
#include <math.h>

#define NN 10000
#define DD 128
#define KSEL 5000
#define BM 64
#define BK 32
#define NST 313                 // ceil(10000/32) k-stages
#define NKPAD (NST * BK)        // 10016 padded k rows
#define JW 10048                // padded j width (157*64)
#define NSPLIT 12
#define NJT 157                 // j tiles of 64
#define CI 2048                 // gather chunk
#define NPART 80                // prep i-parts (125 rows each)

// d_out layout (float32): x_pool[5000*128] | adj_pool[5000*5000] | motif_pool[5000*5000] | scores[10000] | top_idx[5000]
#define XP_OFF   0LL
#define ADJ_OFF  640000LL
#define MOT_OFF  (640000LL + 25000000LL)
#define SC_OFF   (640000LL + 50000000LL)
#define IDX_OFF  (SC_OFF + 10000LL)

// ---------------- scratch (device globals; zero-initialized at load; pads never written) ----------------
__device__ __nv_bfloat16 g_Mbh[(size_t)NKPAD * JW];   // motif bf16 hi, [i][j]
__device__ __nv_bfloat16 g_Mbl[(size_t)NKPAD * JW];   // motif bf16 lo
__device__ float g_colpart[NPART][NN];
__device__ float g_dinv[NN];
__device__ float g_P[(size_t)NN * DD];                 // dinv_i * (x @ W^T), fp32
__device__ __nv_bfloat16 g_Pbh[(size_t)NKPAD * DD];    // P bf16 hi, [i][d]
__device__ __nv_bfloat16 g_Pbl[(size_t)NKPAD * DD];    // P bf16 lo
__device__ float g_Gpart[NSPLIT][(size_t)NN * DD];     // split-K partials
__device__ float g_h[(size_t)NN * DD];
__device__ float g_scores[NN];
__device__ int   g_sel[NN];
__device__ int   g_epos[NN];                           // exclusive scan of g_sel
__device__ int   g_idx[KSEL];

// ---------------- PTX helpers (sm_80-level; compile on compute_103 family target) ----------------
__device__ __forceinline__ uint32_t smem_u32(const void* p) {
    uint32_t a;
    asm("{ .reg .u64 t; cvta.to.shared.u64 t, %1; cvt.u32.u64 %0, t; }" : "=r"(a) : "l"(p));
    return a;
}
__device__ __forceinline__ void cpasync16(uint32_t dst, const void* src) {
    asm volatile("cp.async.cg.shared.global [%0], [%1], 16;" :: "r"(dst), "l"(src));
}
#define CP_COMMIT() asm volatile("cp.async.commit_group;" ::: "memory")
#define CP_WAIT(n)  asm volatile("cp.async.wait_group %0;" :: "n"(n) : "memory")

__device__ __forceinline__ void ldsm4t(uint32_t* r, uint32_t addr) {
    asm volatile("ldmatrix.sync.aligned.m8n8.x4.trans.shared.b16 {%0,%1,%2,%3}, [%4];"
        : "=r"(r[0]), "=r"(r[1]), "=r"(r[2]), "=r"(r[3]) : "r"(addr));
}
__device__ __forceinline__ void mma16816(float* c, const uint32_t* a, const uint32_t* b) {
    asm volatile("mma.sync.aligned.m16n8k16.row.col.f32.bf16.bf16.f32 "
        "{%0,%1,%2,%3}, {%4,%5,%6,%7}, {%8,%9}, {%0,%1,%2,%3};"
        : "+f"(c[0]), "+f"(c[1]), "+f"(c[2]), "+f"(c[3])
        : "r"(a[0]), "r"(a[1]), "r"(a[2]), "r"(a[3]), "r"(b[0]), "r"(b[1]));
}

// ---------------- 1) prep: motif -> bf16 hi/lo [i][j] (padded) + column partial sums ----------------
// grid (10, NPART): 800 CTAs, 125 rows per thread loop -> memory-bound streaming.
__global__ __launch_bounds__(256) void prep_kernel(const float* __restrict__ motif) {
    int part = blockIdx.y;                      // NPART i-parts of 125 rows
    int jg = blockIdx.x * 256 + threadIdx.x;    // group of 4 j's
    int j = jg * 4;
    if (j >= NN) return;
    int r0 = part * (NN / NPART), r1 = r0 + (NN / NPART);
    float s0 = 0.f, s1 = 0.f, s2 = 0.f, s3 = 0.f;
    for (int i = r0; i < r1; i++) {
        float4 v = *(const float4*)&motif[(size_t)i * NN + j];
        s0 += v.x; s1 += v.y; s2 += v.z; s3 += v.w;
        __nv_bfloat162 h01 = __floats2bfloat162_rn(v.x, v.y);
        __nv_bfloat162 h23 = __floats2bfloat162_rn(v.z, v.w);
        __nv_bfloat162 l01 = __floats2bfloat162_rn(v.x - __bfloat162float(h01.x),
                                                   v.y - __bfloat162float(h01.y));
        __nv_bfloat162 l23 = __floats2bfloat162_rn(v.z - __bfloat162float(h23.x),
                                                   v.w - __bfloat162float(h23.y));
        uint2 hw, lw;
        hw.x = *(uint32_t*)&h01; hw.y = *(uint32_t*)&h23;
        lw.x = *(uint32_t*)&l01; lw.y = *(uint32_t*)&l23;
        *(uint2*)&g_Mbh[(size_t)i * JW + j] = hw;
        *(uint2*)&g_Mbl[(size_t)i * JW + j] = lw;
    }
    *(float4*)&g_colpart[part][j] = make_float4(s0, s1, s2, s3);
}

// ---------------- 2) deg -> dinv ----------------
__global__ __launch_bounds__(256) void dinv_kernel() {
    int j = blockIdx.x * 256 + threadIdx.x;
    if (j >= NN) return;
    float d = 1.0f;  // +I diagonal
    #pragma unroll 8
    for (int p = 0; p < NPART; p++) d += g_colpart[p][j];
    g_dinv[j] = 1.0f / sqrtf(d);
}

// ---------------- 3) P[i,d] = dinv[i]*(x@W^T); also emit bf16 hi/lo in [i][d] ----------------
__global__ __launch_bounds__(128) void compute_P_kernel(const float* __restrict__ x,
                                                        const float* __restrict__ W) {
    __shared__ float smX[16][128];
    int tid = threadIdx.x;   // = d
    int i0 = blockIdx.x * 16;
    for (int f = tid; f < 16 * 32; f += 128) {
        int r = f >> 5, c = (f & 31) * 4;
        *(float4*)&smX[r][c] = *(const float4*)&x[(size_t)(i0 + r) * DD + c];
    }
    __syncthreads();
    float acc[16];
    #pragma unroll
    for (int r = 0; r < 16; r++) acc[r] = 0.f;
    const float* wrow = W + (size_t)tid * DD;
    for (int e = 0; e < DD; e += 4) {
        float4 w4 = *(const float4*)&wrow[e];
        #pragma unroll
        for (int r = 0; r < 16; r++) {
            float4 x4 = *(const float4*)&smX[r][e];
            acc[r] += x4.x * w4.x + x4.y * w4.y + x4.z * w4.z + x4.w * w4.w;
        }
    }
    #pragma unroll
    for (int r = 0; r < 16; r++) {
        int gi = i0 + r;
        float p = g_dinv[gi] * acc[r];
        g_P[(size_t)gi * DD + tid] = p;
        __nv_bfloat16 hb = __float2bfloat16(p);
        g_Pbh[(size_t)gi * DD + tid] = hb;
        g_Pbl[(size_t)gi * DD + tid] = __float2bfloat16(p - __bfloat162float(hb));
    }
}

// ---------------- 4) HMMA GEMM: G[j,d] = sum_i motif[i,j]*P[i,d], bf16 hi/lo x3 ----------------
// Both operands pre-split bf16 in K-major global memory (zero-padded) -> pure cp.async staging.
__global__ __launch_bounds__(256) void hmma_gemm_kernel() {
    extern __shared__ __align__(128) char dynsm[];
    const uint32_t smbase = smem_u32(dynsm);
    const uint32_t A_h = smbase;             // [2][32][64] bf16 : 2 x 4096B
    const uint32_t A_l = smbase + 8192;
    const uint32_t B_h = smbase + 16384;     // [2][32][128] bf16: 2 x 8192B
    const uint32_t B_l = smbase + 32768;     // total 49152B

    const int tid = threadIdx.x;
    const int lane = tid & 31;
    const int wid = tid >> 5;
    const int wm = wid & 1;      // 2 warp-rows (m)
    const int wn = wid >> 1;     // 4 warp-cols (n)
    const int j0 = blockIdx.x * BM;
    const int split = blockIdx.y;
    const int sbeg = (split == 0) ? 0 : (26 * split + 1);   // split0: 27 stages, rest 26
    const int ns = (split == 0) ? 27 : 26;

    // A loader: thread -> (k row ak, 16B j-chunk aj)
    const int ak = tid >> 3;
    const int aj = tid & 7;
    const uint32_t aOff = (uint32_t)ak * 128 + (uint32_t)(aj ^ (ak & 7)) * 16;
    const __nv_bfloat16* aSrcH = g_Mbh + (size_t)ak * JW + j0 + aj * 8;
    const __nv_bfloat16* aSrcL = g_Mbl + (size_t)ak * JW + j0 + aj * 8;

    // B loader: thread -> (k row bk, chunks bc and bc+8)
    const int bk = tid >> 3;
    const int bc = tid & 7;
    const uint32_t bOff0 = (uint32_t)bk * 256 + (uint32_t)(bc ^ (bk & 7)) * 16;
    const uint32_t bOff1 = bOff0 + 128;
    const __nv_bfloat16* bSrcH = g_Pbh + (size_t)bk * DD + bc * 8;
    const __nv_bfloat16* bSrcL = g_Pbl + (size_t)bk * DD + bc * 8;

    float acc[2][4][4];
    #pragma unroll
    for (int mt = 0; mt < 2; mt++)
        #pragma unroll
        for (int nt = 0; nt < 4; nt++)
            #pragma unroll
            for (int q = 0; q < 4; q++) acc[mt][nt][q] = 0.f;

#define CP_STAGE(t) do { \
    size_t _k = (size_t)(sbeg + (t)) * BK; \
    uint32_t _ab = ((t) & 1) * 4096u, _bb = ((t) & 1) * 8192u; \
    cpasync16(A_h + _ab + aOff, aSrcH + _k * JW); \
    cpasync16(A_l + _ab + aOff, aSrcL + _k * JW); \
    cpasync16(B_h + _bb + bOff0, bSrcH + _k * DD); \
    cpasync16(B_h + _bb + bOff1, bSrcH + _k * DD + 64); \
    cpasync16(B_l + _bb + bOff0, bSrcL + _k * DD); \
    cpasync16(B_l + _bb + bOff1, bSrcL + _k * DD + 64); \
    CP_COMMIT(); \
} while (0)

    CP_STAGE(0);
    CP_STAGE(1);

    for (int t = 0; t < ns; t++) {
        const int b = t & 1;
        if (t + 1 < ns) { CP_WAIT(1); } else { CP_WAIT(0); }
        __syncthreads();

        const uint32_t Ah = A_h + b * 4096u, Al = A_l + b * 4096u;
        const uint32_t Bh = B_h + b * 8192u, Bl = B_l + b * 8192u;
        #pragma unroll
        for (int kb = 0; kb < 2; kb++) {
            uint32_t ah[2][4], al[2][4], bh[2][4], bl[2][4];
            const int krA = kb * 16 + (lane & 7) + ((lane & 16) ? 8 : 0);
            #pragma unroll
            for (int mt = 0; mt < 2; mt++) {
                uint32_t ch = (uint32_t)((wm * 4 + mt * 2 + ((lane & 8) ? 1 : 0)) ^ (krA & 7));
                uint32_t ad = (uint32_t)krA * 128 + ch * 16;
                ldsm4t(ah[mt], Ah + ad);
                ldsm4t(al[mt], Al + ad);
            }
            const int krB = kb * 16 + (lane & 7) + ((lane & 8) ? 8 : 0);
            #pragma unroll
            for (int np = 0; np < 2; np++) {
                uint32_t c = (uint32_t)(wn * 4 + np * 2 + ((lane & 16) ? 1 : 0));
                uint32_t csw = (c & 8u) | ((c ^ (uint32_t)krB) & 7u);
                uint32_t bd = (uint32_t)krB * 256 + csw * 16;
                ldsm4t(bh[np], Bh + bd);
                ldsm4t(bl[np], Bl + bd);
            }
            #pragma unroll
            for (int mt = 0; mt < 2; mt++)
                #pragma unroll
                for (int nt = 0; nt < 4; nt++) {
                    const int np = nt >> 1, hf = nt & 1;
                    uint32_t bhp[2] = {bh[np][hf * 2], bh[np][hf * 2 + 1]};
                    uint32_t blp[2] = {bl[np][hf * 2], bl[np][hf * 2 + 1]};
                    mma16816(acc[mt][nt], ah[mt], bhp);   // hi*hi
                    mma16816(acc[mt][nt], ah[mt], blp);   // hi*lo
                    mma16816(acc[mt][nt], al[mt], bhp);   // lo*hi
                }
        }
        __syncthreads();
        if (t + 2 < ns) CP_STAGE(t + 2);
    }
#undef CP_STAGE

    // store partial G
    float* G = g_Gpart[split];
    #pragma unroll
    for (int mt = 0; mt < 2; mt++)
        #pragma unroll
        for (int nt = 0; nt < 4; nt++) {
            int j = j0 + wm * 32 + mt * 16 + (lane >> 2);
            int d = wn * 32 + nt * 8 + (lane & 3) * 2;
            if (j < NN) {
                float2 v = make_float2(acc[mt][nt][0], acc[mt][nt][1]);
                *(float2*)(G + (size_t)j * DD + d) = v;
            }
            if (j + 8 < NN) {
                float2 v = make_float2(acc[mt][nt][2], acc[mt][nt][3]);
                *(float2*)(G + (size_t)(j + 8) * DD + d) = v;
            }
        }
}

// ---------------- 5) h = tanh(dinv_j*(sum G + P_j) + b); scores ----------------
__global__ __launch_bounds__(128) void epilogue_kernel(const float* __restrict__ b_gcn,
                                                       const float* __restrict__ w_score,
                                                       const float* __restrict__ b_score,
                                                       float* __restrict__ out) {
    int j = blockIdx.x;
    int d = threadIdx.x;
    size_t o = (size_t)j * DD + d;
    float g = g_P[o];
    #pragma unroll
    for (int s = 0; s < NSPLIT; s++) g += g_Gpart[s][o];
    float hv = tanhf(g_dinv[j] * g + b_gcn[d]);
    g_h[o] = hv;
    float v = hv * w_score[d];
    #pragma unroll
    for (int off = 16; off > 0; off >>= 1) v += __shfl_down_sync(0xffffffffu, v, off);
    __shared__ float ws[4];
    if ((d & 31) == 0) ws[d >> 5] = v;
    __syncthreads();
    if (d == 0) {
        float sc = ((ws[0] + ws[1]) + (ws[2] + ws[3])) + b_score[0];
        g_scores[j] = sc;
        out[SC_OFF + j] = sc;
    }
}

// ---------------- 6) top-k via exact rank (matches lax.top_k stable ties) ----------------
__global__ __launch_bounds__(256) void topk_rank_kernel() {
    __shared__ float ss[NN];
    int tid = threadIdx.x;
    for (int f = tid; f < NN; f += 256) ss[f] = g_scores[f];
    __syncthreads();
    int j = blockIdx.x * 256 + tid;
    if (j >= NN) return;
    float sj = ss[j];
    int rank = 0;
    for (int i = 0; i < NN; i++) {
        float si = ss[i];
        rank += (si > sj) ? 1 : ((si == sj && i < j) ? 1 : 0);
    }
    g_sel[j] = (rank < KSEL) ? 1 : 0;
}

// ---------------- 7) compact selected indices (ascending) + exclusive scan ----------------
__global__ __launch_bounds__(256) void compact_kernel(float* __restrict__ out) {
    __shared__ int wsum[8];
    __shared__ int carry;
    int tid = threadIdx.x, lane = tid & 31, wid = tid >> 5;
    if (tid == 0) carry = 0;
    __syncthreads();
    for (int base = 0; base < NN; base += 256) {
        int j = base + tid;
        int f = (j < NN) ? g_sel[j] : 0;
        int xv = f;
        #pragma unroll
        for (int o = 1; o < 32; o <<= 1) {
            int y = __shfl_up_sync(0xffffffffu, xv, o);
            if (lane >= o) xv += y;
        }
        if (lane == 31) wsum[wid] = xv;
        __syncthreads();
        int woff = 0;
        #pragma unroll
        for (int w = 0; w < 8; w++) if (w < wid) woff += wsum[w];
        int incl = xv + woff;
        int pos = carry + incl - f;
        if (j < NN) {
            g_epos[j] = pos;
            if (f) {
                g_idx[pos] = j;
                out[IDX_OFF + pos] = (float)j;
            }
        }
        __syncthreads();
        if (tid == 255) carry += incl;
        __syncthreads();
    }
}

// ---------------- 8) x_pool gather ----------------
__global__ __launch_bounds__(128) void gather_x_kernel(float* __restrict__ out) {
    int r = blockIdx.x;
    int d = threadIdx.x;
    int ir = g_idx[r];
    out[XP_OFF + (size_t)r * DD + d] = g_h[(size_t)ir * DD + d];
}

// ---------------- 9) adjacency/motif pool gathers (smem-staged, coalesced DRAM reads) ----------------
__global__ __launch_bounds__(256) void gather_pools_kernel(const float* __restrict__ adj,
                                                           const float* __restrict__ motif,
                                                           float* __restrict__ out) {
    __shared__ float smA[CI];
    __shared__ float smM[CI];
    __shared__ int scr[2];
    int tid = threadIdx.x;
    int r = blockIdx.x;
    int ir = g_idx[r];
    const float* arow = adj   + (size_t)ir * NN;
    const float* mrow = motif + (size_t)ir * NN;
    float* oa = out + ADJ_OFF + (size_t)r * KSEL;
    float* om = out + MOT_OFF + (size_t)r * KSEL;

    for (int q0 = 0; q0 < NN; q0 += CI) {
        int qn = min(CI, NN - q0);
        for (int f = tid * 4; f < qn; f += 1024) {
            *(float4*)&smA[f] = *(const float4*)&arow[q0 + f];
            *(float4*)&smM[f] = *(const float4*)&mrow[q0 + f];
        }
        if (tid == 0) {
            scr[0] = g_epos[q0];
            scr[1] = (q0 + CI < NN) ? g_epos[q0 + CI] : KSEL;
        }
        __syncthreads();
        int c0 = scr[0], c1 = scr[1];
        for (int c = c0 + tid; c < c1; c += 256) {
            int ic = g_idx[c] - q0;
            oa[c] = smA[ic];
            om[c] = smM[ic];
        }
        __syncthreads();
    }
}

// ---------------- launch ----------------
extern "C" void kernel_launch(void* const* d_in, const int* in_sizes, int n_in,
                              void* d_out, int out_size) {
    const float* x       = (const float*)d_in[0];
    const float* adj     = (const float*)d_in[1];
    const float* motif   = (const float*)d_in[2];
    const float* W       = (const float*)d_in[3];
    const float* b_gcn   = (const float*)d_in[4];
    const float* w_score = (const float*)d_in[5];
    const float* b_score = (const float*)d_in[6];
    float* out = (float*)d_out;

    prep_kernel<<<dim3(10, NPART), 256>>>(motif);
    dinv_kernel<<<(NN + 255) / 256, 256>>>();
    compute_P_kernel<<<NN / 16, 128>>>(x, W);
    hmma_gemm_kernel<<<dim3(NJT, NSPLIT), 256, 49152>>>();
    epilogue_kernel<<<NN, 128>>>(b_gcn, w_score, b_score, out);
    topk_rank_kernel<<<(NN + 255) / 256, 256>>>();
    compact_kernel<<<1, 256>>>(out);
    gather_x_kernel<<<KSEL, 128>>>(out);
    gather_pools_kernel<<<KSEL, 256>>>(adj, motif, out);
}

// round 13
// speedup vs baseline: 1.7306x; 1.3036x over previous
#include <cuda_runtime.h>
#include <cuda_bf16.h>
#include <cstdint>
#include <math.h>

#define NN 10000
#define DD 128
#define KSEL 5000
#define BM 64
#define BK 32
#define NST 313                 // ceil(10000/32) k-stages total
#define NKPAD (NST * BK)        // 10016 padded k rows (for B only)
#define NSPLIT 12
#define NJT 157                 // j tiles of 64
#define CI 2048                 // gather chunk
#define NPART 20                // colsum i-parts (500 rows each)

// d_out layout (float32): x_pool[5000*128] | adj_pool[5000*5000] | motif_pool[5000*5000] | scores[10000] | top_idx[5000]
#define XP_OFF   0LL
#define ADJ_OFF  640000LL
#define MOT_OFF  (640000LL + 25000000LL)
#define SC_OFF   (640000LL + 50000000LL)
#define IDX_OFF  (SC_OFF + 10000LL)

// ---------------- scratch (device globals; zero-initialized at load; pads never written) ----------------
__device__ float g_colpart[NPART][NN];
__device__ float g_dinv[NN];
__device__ float g_P[(size_t)NN * DD];                 // dinv_i * (x @ W^T), fp32
__device__ __nv_bfloat16 g_Pbh[(size_t)NKPAD * DD];    // P bf16 hi, [i][d], rows >= NN stay zero
__device__ __nv_bfloat16 g_Pbl[(size_t)NKPAD * DD];    // P bf16 lo
__device__ float g_Gpart[NSPLIT][(size_t)NN * DD];     // split-K partials
__device__ float g_h[(size_t)NN * DD];
__device__ float g_scores[NN];
__device__ int   g_sel[NN];
__device__ int   g_epos[NN];                           // exclusive scan of g_sel
__device__ int   g_idx[KSEL];

// ---------------- PTX helpers (sm_80-level; compile on compute_103 family target) ----------------
__device__ __forceinline__ uint32_t smem_u32(const void* p) {
    uint32_t a;
    asm("{ .reg .u64 t; cvta.to.shared.u64 t, %1; cvt.u32.u64 %0, t; }" : "=r"(a) : "l"(p));
    return a;
}
__device__ __forceinline__ void cpasync16(uint32_t dst, const void* src) {
    asm volatile("cp.async.cg.shared.global [%0], [%1], 16;" :: "r"(dst), "l"(src));
}
#define CP_COMMIT() asm volatile("cp.async.commit_group;" ::: "memory")
#define CP_WAIT(n)  asm volatile("cp.async.wait_group %0;" :: "n"(n) : "memory")

__device__ __forceinline__ void sts128(uint32_t addr, uint32_t a, uint32_t b, uint32_t c, uint32_t d) {
    asm volatile("st.shared.v4.b32 [%0], {%1,%2,%3,%4};" :: "r"(addr), "r"(a), "r"(b), "r"(c), "r"(d));
}
__device__ __forceinline__ void ldsm4t(uint32_t* r, uint32_t addr) {
    asm volatile("ldmatrix.sync.aligned.m8n8.x4.trans.shared.b16 {%0,%1,%2,%3}, [%4];"
        : "=r"(r[0]), "=r"(r[1]), "=r"(r[2]), "=r"(r[3]) : "r"(addr));
}
__device__ __forceinline__ void mma16816(float* c, const uint32_t* a, const uint32_t* b) {
    asm volatile("mma.sync.aligned.m16n8k16.row.col.f32.bf16.bf16.f32 "
        "{%0,%1,%2,%3}, {%4,%5,%6,%7}, {%8,%9}, {%0,%1,%2,%3};"
        : "+f"(c[0]), "+f"(c[1]), "+f"(c[2]), "+f"(c[3])
        : "r"(a[0]), "r"(a[1]), "r"(a[2]), "r"(a[3]), "r"(b[0]), "r"(b[1]));
}

// ---------------- 1) column partial sums of motif (coalesced, 800 CTAs) ----------------
__global__ __launch_bounds__(256) void colsum_kernel(const float* __restrict__ motif) {
    int j = blockIdx.x * 256 + threadIdx.x;
    if (j >= NN) return;
    int part = blockIdx.y;
    int r0 = part * (NN / NPART);
    int r1 = r0 + (NN / NPART);
    float s0 = 0.f, s1 = 0.f, s2 = 0.f, s3 = 0.f;
    for (int i = r0; i < r1; i += 4) {
        s0 += motif[(size_t)(i + 0) * NN + j];
        s1 += motif[(size_t)(i + 1) * NN + j];
        s2 += motif[(size_t)(i + 2) * NN + j];
        s3 += motif[(size_t)(i + 3) * NN + j];
    }
    g_colpart[part][j] = (s0 + s1) + (s2 + s3);
}

// ---------------- 2) deg -> dinv ----------------
__global__ __launch_bounds__(256) void dinv_kernel() {
    int j = blockIdx.x * 256 + threadIdx.x;
    if (j >= NN) return;
    float d = 1.0f;  // +I diagonal
    #pragma unroll
    for (int p = 0; p < NPART; p++) d += g_colpart[p][j];
    g_dinv[j] = 1.0f / sqrtf(d);
}

// ---------------- 3) P[i,d] = dinv[i]*(x@W^T); also emit bf16 hi/lo in [i][d] ----------------
__global__ __launch_bounds__(128) void compute_P_kernel(const float* __restrict__ x,
                                                        const float* __restrict__ W) {
    __shared__ float smX[16][128];
    int tid = threadIdx.x;   // = d
    int i0 = blockIdx.x * 16;
    for (int f = tid; f < 16 * 32; f += 128) {
        int r = f >> 5, c = (f & 31) * 4;
        *(float4*)&smX[r][c] = *(const float4*)&x[(size_t)(i0 + r) * DD + c];
    }
    __syncthreads();
    float acc[16];
    #pragma unroll
    for (int r = 0; r < 16; r++) acc[r] = 0.f;
    const float* wrow = W + (size_t)tid * DD;
    for (int e = 0; e < DD; e += 4) {
        float4 w4 = *(const float4*)&wrow[e];
        #pragma unroll
        for (int r = 0; r < 16; r++) {
            float4 x4 = *(const float4*)&smX[r][e];
            acc[r] += x4.x * w4.x + x4.y * w4.y + x4.z * w4.z + x4.w * w4.w;
        }
    }
    #pragma unroll
    for (int r = 0; r < 16; r++) {
        int gi = i0 + r;
        float p = g_dinv[gi] * acc[r];
        g_P[(size_t)gi * DD + tid] = p;
        __nv_bfloat16 hb = __float2bfloat16(p);
        g_Pbh[(size_t)gi * DD + tid] = hb;
        g_Pbl[(size_t)gi * DD + tid] = __float2bfloat16(p - __bfloat162float(hb));
    }
}

// ---------------- 4) HMMA GEMM: G[j,d] = sum_i motif[i,j]*P[i,d], bf16 hi/lo x3 ----------------
// A staged from fp32 motif (convert in-regs -> smem), B pre-split bf16 via cp.async.
__global__ __launch_bounds__(256) void hmma_gemm_kernel(const float* __restrict__ motif) {
    extern __shared__ __align__(128) char dynsm[];
    const uint32_t smbase = smem_u32(dynsm);
    const uint32_t A_h = smbase;             // [2][32][64] bf16 : 2 x 4096B
    const uint32_t A_l = smbase + 8192;
    const uint32_t B_h = smbase + 16384;     // [2][32][128] bf16: 2 x 8192B
    const uint32_t B_l = smbase + 32768;     // total 49152B

    const int tid = threadIdx.x;
    const int lane = tid & 31;
    const int wid = tid >> 5;
    const int wm = wid & 1;      // 2 warp-rows (m)
    const int wn = wid >> 1;     // 4 warp-cols (n)
    const int j0 = blockIdx.x * BM;
    const int split = blockIdx.y;
    const int sbeg = (split == 0) ? 0 : (26 * split + 1);   // split0: 27 stages, rest 26
    const int ns = (split == 0) ? 27 : 26;

    // A loader: thread -> (k row ak, 8-float j segment aj), LDG fp32 + convert + STS
    const int ak = tid >> 3;
    const int aj = tid & 7;
    const bool jv = (j0 + aj * 8) < NN;              // NN % 8 == 0 -> whole segment validity
    const uint32_t aOff = (uint32_t)ak * 128 + (uint32_t)(aj ^ (ak & 7)) * 16;
    const float* aSrcBase = motif + (size_t)j0 + (size_t)aj * 8;

    // B loader: thread -> (k row bk, chunks bc and bc+8) via cp.async
    const int bk = tid >> 3;
    const int bc = tid & 7;
    const uint32_t bOff0 = (uint32_t)bk * 256 + (uint32_t)(bc ^ (bk & 7)) * 16;
    const uint32_t bOff1 = bOff0 + 128;
    const __nv_bfloat16* bSrcH = g_Pbh + (size_t)bk * DD + bc * 8;
    const __nv_bfloat16* bSrcL = g_Pbl + (size_t)bk * DD + bc * 8;

    float4 areg[2][2];
    float acc[2][4][4];
    #pragma unroll
    for (int mt = 0; mt < 2; mt++)
        #pragma unroll
        for (int nt = 0; nt < 4; nt++)
            #pragma unroll
            for (int q = 0; q < 4; q++) acc[mt][nt][q] = 0.f;

    const float4 z4 = make_float4(0.f, 0.f, 0.f, 0.f);

#define LDG_A(t) do { \
    int _i = (sbeg + (t)) * BK + ak; \
    bool _v = jv && (_i < NN); \
    const float* _p = aSrcBase + (size_t)_i * NN; \
    areg[(t) & 1][0] = _v ? *(const float4*)_p : z4; \
    areg[(t) & 1][1] = _v ? *(const float4*)(_p + 4) : z4; \
} while (0)

#define STS_A(t) do { \
    float4 _v0 = areg[(t) & 1][0], _v1 = areg[(t) & 1][1]; \
    float _f[8] = {_v0.x, _v0.y, _v0.z, _v0.w, _v1.x, _v1.y, _v1.z, _v1.w}; \
    uint32_t _h[4], _l[4]; \
    _Pragma("unroll") \
    for (int _e = 0; _e < 4; _e++) { \
        __nv_bfloat162 _hp = __floats2bfloat162_rn(_f[2 * _e], _f[2 * _e + 1]); \
        __nv_bfloat162 _lp = __floats2bfloat162_rn(_f[2 * _e] - __bfloat162float(_hp.x), \
                                                   _f[2 * _e + 1] - __bfloat162float(_hp.y)); \
        _h[_e] = *(uint32_t*)&_hp; _l[_e] = *(uint32_t*)&_lp; \
    } \
    uint32_t _bo = ((t) & 1) * 4096u + aOff; \
    sts128(A_h + _bo, _h[0], _h[1], _h[2], _h[3]); \
    sts128(A_l + _bo, _l[0], _l[1], _l[2], _l[3]); \
} while (0)

#define CP_B(t) do { \
    size_t _k = (size_t)(sbeg + (t)) * BK; \
    uint32_t _bb = ((t) & 1) * 8192u; \
    cpasync16(B_h + _bb + bOff0, bSrcH + _k * DD); \
    cpasync16(B_h + _bb + bOff1, bSrcH + _k * DD + 64); \
    cpasync16(B_l + _bb + bOff0, bSrcL + _k * DD); \
    cpasync16(B_l + _bb + bOff1, bSrcL + _k * DD + 64); \
    CP_COMMIT(); \
} while (0)

    // prologue
    LDG_A(0); CP_B(0); STS_A(0);
    LDG_A(1); CP_B(1);

    for (int t = 0; t < ns; t++) {
        const int b = t & 1;
        if (t + 2 < ns) LDG_A(t + 2);
        if (t + 1 < ns) STS_A(t + 1);
        if (t + 1 < ns) { CP_WAIT(1); } else { CP_WAIT(0); }
        __syncthreads();

        const uint32_t Ah = A_h + b * 4096u, Al = A_l + b * 4096u;
        const uint32_t Bh = B_h + b * 8192u, Bl = B_l + b * 8192u;
        #pragma unroll
        for (int kb = 0; kb < 2; kb++) {
            uint32_t ah[2][4], al[2][4], bh[2][4], bl[2][4];
            const int krA = kb * 16 + (lane & 7) + ((lane & 16) ? 8 : 0);
            #pragma unroll
            for (int mt = 0; mt < 2; mt++) {
                uint32_t ch = (uint32_t)((wm * 4 + mt * 2 + ((lane & 8) ? 1 : 0)) ^ (krA & 7));
                uint32_t ad = (uint32_t)krA * 128 + ch * 16;
                ldsm4t(ah[mt], Ah + ad);
                ldsm4t(al[mt], Al + ad);
            }
            const int krB = kb * 16 + (lane & 7) + ((lane & 8) ? 8 : 0);
            #pragma unroll
            for (int np = 0; np < 2; np++) {
                uint32_t c = (uint32_t)(wn * 4 + np * 2 + ((lane & 16) ? 1 : 0));
                uint32_t csw = (c & 8u) | ((c ^ (uint32_t)krB) & 7u);
                uint32_t bd = (uint32_t)krB * 256 + csw * 16;
                ldsm4t(bh[np], Bh + bd);
                ldsm4t(bl[np], Bl + bd);
            }
            #pragma unroll
            for (int mt = 0; mt < 2; mt++)
                #pragma unroll
                for (int nt = 0; nt < 4; nt++) {
                    const int np = nt >> 1, hf = nt & 1;
                    uint32_t bhp[2] = {bh[np][hf * 2], bh[np][hf * 2 + 1]};
                    uint32_t blp[2] = {bl[np][hf * 2], bl[np][hf * 2 + 1]};
                    mma16816(acc[mt][nt], ah[mt], bhp);   // hi*hi
                    mma16816(acc[mt][nt], ah[mt], blp);   // hi*lo
                    mma16816(acc[mt][nt], al[mt], bhp);   // lo*hi
                }
        }
        __syncthreads();
        if (t + 2 < ns) CP_B(t + 2);
    }
#undef LDG_A
#undef STS_A
#undef CP_B

    // store partial G
    float* G = g_Gpart[split];
    #pragma unroll
    for (int mt = 0; mt < 2; mt++)
        #pragma unroll
        for (int nt = 0; nt < 4; nt++) {
            int j = j0 + wm * 32 + mt * 16 + (lane >> 2);
            int d = wn * 32 + nt * 8 + (lane & 3) * 2;
            if (j < NN) {
                float2 v = make_float2(acc[mt][nt][0], acc[mt][nt][1]);
                *(float2*)(G + (size_t)j * DD + d) = v;
            }
            if (j + 8 < NN) {
                float2 v = make_float2(acc[mt][nt][2], acc[mt][nt][3]);
                *(float2*)(G + (size_t)(j + 8) * DD + d) = v;
            }
        }
}

// ---------------- 5) h = tanh(dinv_j*(sum G + P_j) + b); scores ----------------
__global__ __launch_bounds__(128) void epilogue_kernel(const float* __restrict__ b_gcn,
                                                       const float* __restrict__ w_score,
                                                       const float* __restrict__ b_score,
                                                       float* __restrict__ out) {
    int j = blockIdx.x;
    int d = threadIdx.x;
    size_t o = (size_t)j * DD + d;
    float g = g_P[o];
    #pragma unroll
    for (int s = 0; s < NSPLIT; s++) g += g_Gpart[s][o];
    float hv = tanhf(g_dinv[j] * g + b_gcn[d]);
    g_h[o] = hv;
    float v = hv * w_score[d];
    #pragma unroll
    for (int off = 16; off > 0; off >>= 1) v += __shfl_down_sync(0xffffffffu, v, off);
    __shared__ float ws[4];
    if ((d & 31) == 0) ws[d >> 5] = v;
    __syncthreads();
    if (d == 0) {
        float sc = ((ws[0] + ws[1]) + (ws[2] + ws[3])) + b_score[0];
        g_scores[j] = sc;
        out[SC_OFF + j] = sc;
    }
}

// ---------------- 6) top-k via exact rank (matches lax.top_k stable ties) ----------------
__global__ __launch_bounds__(256) void topk_rank_kernel() {
    __shared__ float ss[NN];
    int tid = threadIdx.x;
    for (int f = tid; f < NN; f += 256) ss[f] = g_scores[f];
    __syncthreads();
    int j = blockIdx.x * 256 + tid;
    if (j >= NN) return;
    float sj = ss[j];
    int rank = 0;
    for (int i = 0; i < NN; i++) {
        float si = ss[i];
        rank += (si > sj) ? 1 : ((si == sj && i < j) ? 1 : 0);
    }
    g_sel[j] = (rank < KSEL) ? 1 : 0;
}

// ---------------- 7) compact selected indices (ascending) + exclusive scan ----------------
__global__ __launch_bounds__(256) void compact_kernel(float* __restrict__ out) {
    __shared__ int wsum[8];
    __shared__ int carry;
    int tid = threadIdx.x, lane = tid & 31, wid = tid >> 5;
    if (tid == 0) carry = 0;
    __syncthreads();
    for (int base = 0; base < NN; base += 256) {
        int j = base + tid;
        int f = (j < NN) ? g_sel[j] : 0;
        int xv = f;
        #pragma unroll
        for (int o = 1; o < 32; o <<= 1) {
            int y = __shfl_up_sync(0xffffffffu, xv, o);
            if (lane >= o) xv += y;
        }
        if (lane == 31) wsum[wid] = xv;
        __syncthreads();
        int woff = 0;
        #pragma unroll
        for (int w = 0; w < 8; w++) if (w < wid) woff += wsum[w];
        int incl = xv + woff;
        int pos = carry + incl - f;
        if (j < NN) {
            g_epos[j] = pos;
            if (f) {
                g_idx[pos] = j;
                out[IDX_OFF + pos] = (float)j;
            }
        }
        __syncthreads();
        if (tid == 255) carry += incl;
        __syncthreads();
    }
}

// ---------------- 8) x_pool gather ----------------
__global__ __launch_bounds__(128) void gather_x_kernel(float* __restrict__ out) {
    int r = blockIdx.x;
    int d = threadIdx.x;
    int ir = g_idx[r];
    out[XP_OFF + (size_t)r * DD + d] = g_h[(size_t)ir * DD + d];
}

// ---------------- 9) adjacency/motif pool gathers (smem-staged, coalesced DRAM reads) ----------------
__global__ __launch_bounds__(256) void gather_pools_kernel(const float* __restrict__ adj,
                                                           const float* __restrict__ motif,
                                                           float* __restrict__ out) {
    __shared__ float smA[CI];
    __shared__ float smM[CI];
    __shared__ int scr[2];
    int tid = threadIdx.x;
    int r = blockIdx.x;
    int ir = g_idx[r];
    const float* arow = adj   + (size_t)ir * NN;
    const float* mrow = motif + (size_t)ir * NN;
    float* oa = out + ADJ_OFF + (size_t)r * KSEL;
    float* om = out + MOT_OFF + (size_t)r * KSEL;

    for (int q0 = 0; q0 < NN; q0 += CI) {
        int qn = min(CI, NN - q0);
        for (int f = tid * 4; f < qn; f += 1024) {
            *(float4*)&smA[f] = *(const float4*)&arow[q0 + f];
            *(float4*)&smM[f] = *(const float4*)&mrow[q0 + f];
        }
        if (tid == 0) {
            scr[0] = g_epos[q0];
            scr[1] = (q0 + CI < NN) ? g_epos[q0 + CI] : KSEL;
        }
        __syncthreads();
        int c0 = scr[0], c1 = scr[1];
        for (int c = c0 + tid; c < c1; c += 256) {
            int ic = g_idx[c] - q0;
            oa[c] = smA[ic];
            om[c] = smM[ic];
        }
        __syncthreads();
    }
}

// ---------------- launch ----------------
extern "C" void kernel_launch(void* const* d_in, const int* in_sizes, int n_in,
                              void* d_out, int out_size) {
    const float* x       = (const float*)d_in[0];
    const float* adj     = (const float*)d_in[1];
    const float* motif   = (const float*)d_in[2];
    const float* W       = (const float*)d_in[3];
    const float* b_gcn   = (const float*)d_in[4];
    const float* w_score = (const float*)d_in[5];
    const float* b_score = (const float*)d_in[6];
    float* out = (float*)d_out;

    colsum_kernel<<<dim3((NN + 255) / 256, NPART), 256>>>(motif);
    dinv_kernel<<<(NN + 255) / 256, 256>>>();
    compute_P_kernel<<<NN / 16, 128>>>(x, W);
    hmma_gemm_kernel<<<dim3(NJT, NSPLIT), 256, 49152>>>(motif);
    epilogue_kernel<<<NN, 128>>>(b_gcn, w_score, b_score, out);
    topk_rank_kernel<<<(NN + 255) / 256, 256>>>();
    compact_kernel<<<1, 256>>>(out);
    gather_x_kernel<<<KSEL, 128>>>(out);
    gather_pools_kernel<<<KSEL, 256>>>(adj, motif, out);
}

// round 14
// speedup vs baseline: 1.7690x; 1.0222x over previous
#include <cuda_runtime.h>
#include <cuda_bf16.h>
#include <cstdint>
#include <math.h>

#define NN 10000
#define DD 128
#define KSEL 5000
#define BM 64
#define BK 32
#define NST 313                 // ceil(10000/32) k-stages total
#define NKPAD (NST * BK)        // 10016 padded k rows (for B only)
#define NSPLIT 15
#define NJT 157                 // j tiles of 64
#define CI 2048                 // gather chunk
#define NPART 20                // colsum i-parts (500 rows each)

// d_out layout (float32): x_pool[5000*128] | adj_pool[5000*5000] | motif_pool[5000*5000] | scores[10000] | top_idx[5000]
#define XP_OFF   0LL
#define ADJ_OFF  640000LL
#define MOT_OFF  (640000LL + 25000000LL)
#define SC_OFF   (640000LL + 50000000LL)
#define IDX_OFF  (SC_OFF + 10000LL)

// ---------------- scratch (device globals; zero-initialized at load; pads never written) ----------------
__device__ float g_colpart[NPART][NN];
__device__ float g_dinv[NN];
__device__ float g_P[(size_t)NN * DD];                 // dinv_i * (x @ W^T), fp32
__device__ __nv_bfloat16 g_Pbh[(size_t)NKPAD * DD];    // P bf16 hi, [i][d], rows >= NN stay zero
__device__ __nv_bfloat16 g_Pbl[(size_t)NKPAD * DD];    // P bf16 lo
__device__ float g_Gpart[NSPLIT][(size_t)NN * DD];     // split-K partials
__device__ float g_h[(size_t)NN * DD];
__device__ float g_scores[NN];
__device__ int   g_sel[NN];
__device__ int   g_epos[NN];                           // exclusive scan of g_sel
__device__ int   g_idx[KSEL];

// ---------------- PTX helpers (sm_80-level; compile on compute_103 family target) ----------------
__device__ __forceinline__ uint32_t smem_u32(const void* p) {
    uint32_t a;
    asm("{ .reg .u64 t; cvta.to.shared.u64 t, %1; cvt.u32.u64 %0, t; }" : "=r"(a) : "l"(p));
    return a;
}
__device__ __forceinline__ void cpasync16(uint32_t dst, const void* src) {
    asm volatile("cp.async.cg.shared.global [%0], [%1], 16;" :: "r"(dst), "l"(src));
}
#define CP_COMMIT() asm volatile("cp.async.commit_group;" ::: "memory")
#define CP_WAIT(n)  asm volatile("cp.async.wait_group %0;" :: "n"(n) : "memory")

__device__ __forceinline__ void sts128(uint32_t addr, uint32_t a, uint32_t b, uint32_t c, uint32_t d) {
    asm volatile("st.shared.v4.b32 [%0], {%1,%2,%3,%4};" :: "r"(addr), "r"(a), "r"(b), "r"(c), "r"(d));
}
__device__ __forceinline__ void ldsm4t(uint32_t* r, uint32_t addr) {
    asm volatile("ldmatrix.sync.aligned.m8n8.x4.trans.shared.b16 {%0,%1,%2,%3}, [%4];"
        : "=r"(r[0]), "=r"(r[1]), "=r"(r[2]), "=r"(r[3]) : "r"(addr));
}
__device__ __forceinline__ void mma16816(float* c, const uint32_t* a, const uint32_t* b) {
    asm volatile("mma.sync.aligned.m16n8k16.row.col.f32.bf16.bf16.f32 "
        "{%0,%1,%2,%3}, {%4,%5,%6,%7}, {%8,%9}, {%0,%1,%2,%3};"
        : "+f"(c[0]), "+f"(c[1]), "+f"(c[2]), "+f"(c[3])
        : "r"(a[0]), "r"(a[1]), "r"(a[2]), "r"(a[3]), "r"(b[0]), "r"(b[1]));
}

// ---------------- 1) column partial sums of motif (coalesced, full-chip) ----------------
__global__ __launch_bounds__(256) void colsum_kernel(const float* __restrict__ motif) {
    int j = blockIdx.x * 256 + threadIdx.x;
    if (j >= NN) return;
    int part = blockIdx.y;
    int r0 = part * (NN / NPART);
    int r1 = r0 + (NN / NPART);
    float s0 = 0.f, s1 = 0.f, s2 = 0.f, s3 = 0.f;
    for (int i = r0; i < r1; i += 4) {
        s0 += motif[(size_t)(i + 0) * NN + j];
        s1 += motif[(size_t)(i + 1) * NN + j];
        s2 += motif[(size_t)(i + 2) * NN + j];
        s3 += motif[(size_t)(i + 3) * NN + j];
    }
    g_colpart[part][j] = (s0 + s1) + (s2 + s3);
}

// ---------------- 2) deg -> dinv ----------------
__global__ __launch_bounds__(256) void dinv_kernel() {
    int j = blockIdx.x * 256 + threadIdx.x;
    if (j >= NN) return;
    float d = 1.0f;  // +I diagonal
    #pragma unroll
    for (int p = 0; p < NPART; p++) d += g_colpart[p][j];
    g_dinv[j] = 1.0f / sqrtf(d);
}

// ---------------- 3) P[i,d] = dinv[i]*(x@W^T); also emit bf16 hi/lo in [i][d] ----------------
__global__ __launch_bounds__(128) void compute_P_kernel(const float* __restrict__ x,
                                                        const float* __restrict__ W) {
    __shared__ float smX[16][128];
    int tid = threadIdx.x;   // = d
    int i0 = blockIdx.x * 16;
    for (int f = tid; f < 16 * 32; f += 128) {
        int r = f >> 5, c = (f & 31) * 4;
        *(float4*)&smX[r][c] = *(const float4*)&x[(size_t)(i0 + r) * DD + c];
    }
    __syncthreads();
    float acc[16];
    #pragma unroll
    for (int r = 0; r < 16; r++) acc[r] = 0.f;
    const float* wrow = W + (size_t)tid * DD;
    for (int e = 0; e < DD; e += 4) {
        float4 w4 = *(const float4*)&wrow[e];
        #pragma unroll
        for (int r = 0; r < 16; r++) {
            float4 x4 = *(const float4*)&smX[r][e];
            acc[r] += x4.x * w4.x + x4.y * w4.y + x4.z * w4.z + x4.w * w4.w;
        }
    }
    #pragma unroll
    for (int r = 0; r < 16; r++) {
        int gi = i0 + r;
        float p = g_dinv[gi] * acc[r];
        g_P[(size_t)gi * DD + tid] = p;
        __nv_bfloat16 hb = __float2bfloat16(p);
        g_Pbh[(size_t)gi * DD + tid] = hb;
        g_Pbl[(size_t)gi * DD + tid] = __float2bfloat16(p - __bfloat162float(hb));
    }
}

// ---------------- 4) HMMA GEMM: G[j,d] = sum_i motif[i,j]*P[i,d], bf16 hi/lo x3 ----------------
// 128 threads, warp grid 2x2, warp tile 32m x 64n. A from fp32 motif (convert in regs),
// B pre-split bf16 via cp.async. 2-deep smem pipeline, single A-staging reg buffer.
__global__ __launch_bounds__(128, 4) void hmma_gemm_kernel(const float* __restrict__ motif) {
    extern __shared__ __align__(128) char dynsm[];
    const uint32_t smbase = smem_u32(dynsm);
    const uint32_t A_h = smbase;             // [2][32][64] bf16 : 2 x 4096B
    const uint32_t A_l = smbase + 8192;
    const uint32_t B_h = smbase + 16384;     // [2][32][128] bf16: 2 x 8192B
    const uint32_t B_l = smbase + 32768;     // total 49152B

    const int tid = threadIdx.x;
    const int lane = tid & 31;
    const int wid = tid >> 5;
    const int wm = wid & 1;      // 2 warp-rows (m: 32 each)
    const int wn = wid >> 1;     // 2 warp-cols (n: 64 each)
    const int j0 = blockIdx.x * BM;
    const int split = blockIdx.y;
    const int sbeg = (split * NST) / NSPLIT;
    const int ns = ((split + 1) * NST) / NSPLIT - sbeg;

    // A loader: 4 threads per k-row, each 16 floats (2 chunks of 8)
    const int ak = tid >> 2;
    const int aseg = tid & 3;
    const bool jv = (j0 + aseg * 16) < NN;           // NN % 16 == 0 -> whole-segment validity
    const uint32_t aOff0 = (uint32_t)ak * 128 + (uint32_t)((aseg * 2)     ^ (ak & 7)) * 16;
    const uint32_t aOff1 = (uint32_t)ak * 128 + (uint32_t)((aseg * 2 + 1) ^ (ak & 7)) * 16;
    const float* aSrcBase = motif + (size_t)j0 + (size_t)aseg * 16;

    // B loader: 4 threads per k-row, each 4 chunks (64B) per matrix
    const int bk = tid >> 2;
    const int bq = tid & 3;
    uint32_t bOff[4];
    #pragma unroll
    for (int e = 0; e < 4; e++) {
        uint32_t c = (uint32_t)(bq * 4 + e);
        bOff[e] = (uint32_t)bk * 256 + (((c & 8u) | ((c ^ (uint32_t)(bk & 7)) & 7u)) * 16);
    }
    const __nv_bfloat16* bSrcH = g_Pbh + (size_t)bk * DD + bq * 32;
    const __nv_bfloat16* bSrcL = g_Pbl + (size_t)bk * DD + bq * 32;

    float4 areg[4];
    float acc[2][8][4];
    #pragma unroll
    for (int mt = 0; mt < 2; mt++)
        #pragma unroll
        for (int nt = 0; nt < 8; nt++)
            #pragma unroll
            for (int q = 0; q < 4; q++) acc[mt][nt][q] = 0.f;

    const float4 z4 = make_float4(0.f, 0.f, 0.f, 0.f);

#define LDG_A(t) do { \
    int _i = (sbeg + (t)) * BK + ak; \
    bool _v = jv && (_i < NN); \
    const float* _p = aSrcBase + (size_t)_i * NN; \
    areg[0] = _v ? *(const float4*)_p : z4; \
    areg[1] = _v ? *(const float4*)(_p + 4) : z4; \
    areg[2] = _v ? *(const float4*)(_p + 8) : z4; \
    areg[3] = _v ? *(const float4*)(_p + 12) : z4; \
} while (0)

#define STS_A(t) do { \
    float _f[16] = {areg[0].x, areg[0].y, areg[0].z, areg[0].w, \
                    areg[1].x, areg[1].y, areg[1].z, areg[1].w, \
                    areg[2].x, areg[2].y, areg[2].z, areg[2].w, \
                    areg[3].x, areg[3].y, areg[3].z, areg[3].w}; \
    uint32_t _h[8], _l[8]; \
    _Pragma("unroll") \
    for (int _e = 0; _e < 8; _e++) { \
        __nv_bfloat162 _hp = __floats2bfloat162_rn(_f[2 * _e], _f[2 * _e + 1]); \
        __nv_bfloat162 _lp = __floats2bfloat162_rn(_f[2 * _e] - __bfloat162float(_hp.x), \
                                                   _f[2 * _e + 1] - __bfloat162float(_hp.y)); \
        _h[_e] = *(uint32_t*)&_hp; _l[_e] = *(uint32_t*)&_lp; \
    } \
    uint32_t _bo = ((t) & 1) * 4096u; \
    sts128(A_h + _bo + aOff0, _h[0], _h[1], _h[2], _h[3]); \
    sts128(A_h + _bo + aOff1, _h[4], _h[5], _h[6], _h[7]); \
    sts128(A_l + _bo + aOff0, _l[0], _l[1], _l[2], _l[3]); \
    sts128(A_l + _bo + aOff1, _l[4], _l[5], _l[6], _l[7]); \
} while (0)

#define CP_B(t) do { \
    size_t _k = (size_t)(sbeg + (t)) * BK * DD; \
    uint32_t _bb = ((t) & 1) * 8192u; \
    _Pragma("unroll") \
    for (int _e = 0; _e < 4; _e++) { \
        cpasync16(B_h + _bb + bOff[_e], bSrcH + _k + _e * 8); \
        cpasync16(B_l + _bb + bOff[_e], bSrcL + _k + _e * 8); \
    } \
    CP_COMMIT(); \
} while (0)

    // prologue
    LDG_A(0); CP_B(0); STS_A(0);
    LDG_A(1); CP_B(1);

    for (int t = 0; t < ns; t++) {
        const int b = t & 1;
        if (t + 1 < ns) STS_A(t + 1);
        if (t + 1 < ns) { CP_WAIT(1); } else { CP_WAIT(0); }
        __syncthreads();
        if (t + 2 < ns) LDG_A(t + 2);

        const uint32_t Ah = A_h + b * 4096u, Al = A_l + b * 4096u;
        const uint32_t Bh = B_h + b * 8192u, Bl = B_l + b * 8192u;
        #pragma unroll
        for (int kb = 0; kb < 2; kb++) {
            uint32_t ah[2][4], al[2][4];
            const int krA = kb * 16 + (lane & 7) + ((lane & 16) ? 8 : 0);
            #pragma unroll
            for (int mt = 0; mt < 2; mt++) {
                uint32_t ch = (uint32_t)((wm * 4 + mt * 2 + ((lane & 8) ? 1 : 0)) ^ (krA & 7));
                uint32_t ad = (uint32_t)krA * 128 + ch * 16;
                ldsm4t(ah[mt], Ah + ad);
                ldsm4t(al[mt], Al + ad);
            }
            const int krB = kb * 16 + (lane & 7) + ((lane & 8) ? 8 : 0);
            #pragma unroll
            for (int np = 0; np < 4; np++) {
                uint32_t c = (uint32_t)(wn * 8 + np * 2 + ((lane & 16) ? 1 : 0));
                uint32_t csw = (c & 8u) | ((c ^ (uint32_t)krB) & 7u);
                uint32_t bd = (uint32_t)krB * 256 + csw * 16;
                uint32_t bh[4], bl[4];
                ldsm4t(bh, Bh + bd);
                ldsm4t(bl, Bl + bd);
                #pragma unroll
                for (int mt = 0; mt < 2; mt++)
                    #pragma unroll
                    for (int hf = 0; hf < 2; hf++) {
                        const int nt = np * 2 + hf;
                        uint32_t bhp[2] = {bh[hf * 2], bh[hf * 2 + 1]};
                        uint32_t blp[2] = {bl[hf * 2], bl[hf * 2 + 1]};
                        mma16816(acc[mt][nt], ah[mt], bhp);   // hi*hi
                        mma16816(acc[mt][nt], ah[mt], blp);   // hi*lo
                        mma16816(acc[mt][nt], al[mt], bhp);   // lo*hi
                    }
            }
        }
        __syncthreads();
        if (t + 2 < ns) CP_B(t + 2);
    }
#undef LDG_A
#undef STS_A
#undef CP_B

    // store partial G
    float* G = g_Gpart[split];
    #pragma unroll
    for (int mt = 0; mt < 2; mt++)
        #pragma unroll
        for (int nt = 0; nt < 8; nt++) {
            int j = j0 + wm * 32 + mt * 16 + (lane >> 2);
            int d = wn * 64 + nt * 8 + (lane & 3) * 2;
            if (j < NN) {
                float2 v = make_float2(acc[mt][nt][0], acc[mt][nt][1]);
                *(float2*)(G + (size_t)j * DD + d) = v;
            }
            if (j + 8 < NN) {
                float2 v = make_float2(acc[mt][nt][2], acc[mt][nt][3]);
                *(float2*)(G + (size_t)(j + 8) * DD + d) = v;
            }
        }
}

// ---------------- 5) h = tanh(dinv_j*(sum G + P_j) + b); scores ----------------
__global__ __launch_bounds__(128) void epilogue_kernel(const float* __restrict__ b_gcn,
                                                       const float* __restrict__ w_score,
                                                       const float* __restrict__ b_score,
                                                       float* __restrict__ out) {
    int j = blockIdx.x;
    int d = threadIdx.x;
    size_t o = (size_t)j * DD + d;
    float g = g_P[o];
    #pragma unroll
    for (int s = 0; s < NSPLIT; s++) g += g_Gpart[s][o];
    float hv = tanhf(g_dinv[j] * g + b_gcn[d]);
    g_h[o] = hv;
    float v = hv * w_score[d];
    #pragma unroll
    for (int off = 16; off > 0; off >>= 1) v += __shfl_down_sync(0xffffffffu, v, off);
    __shared__ float ws[4];
    if ((d & 31) == 0) ws[d >> 5] = v;
    __syncthreads();
    if (d == 0) {
        float sc = ((ws[0] + ws[1]) + (ws[2] + ws[3])) + b_score[0];
        g_scores[j] = sc;
        out[SC_OFF + j] = sc;
    }
}

// ---------------- 6) top-k via exact rank (matches lax.top_k stable ties) ----------------
__global__ __launch_bounds__(256) void topk_rank_kernel() {
    __shared__ float ss[NN];
    int tid = threadIdx.x;
    for (int f = tid; f < NN; f += 256) ss[f] = g_scores[f];
    __syncthreads();
    int j = blockIdx.x * 256 + tid;
    if (j >= NN) return;
    float sj = ss[j];
    int rank = 0;
    for (int i = 0; i < NN; i++) {
        float si = ss[i];
        rank += (si > sj) ? 1 : ((si == sj && i < j) ? 1 : 0);
    }
    g_sel[j] = (rank < KSEL) ? 1 : 0;
}

// ---------------- 7) compact selected indices (ascending) + exclusive scan ----------------
__global__ __launch_bounds__(256) void compact_kernel(float* __restrict__ out) {
    __shared__ int wsum[8];
    __shared__ int carry;
    int tid = threadIdx.x, lane = tid & 31, wid = tid >> 5;
    if (tid == 0) carry = 0;
    __syncthreads();
    for (int base = 0; base < NN; base += 256) {
        int j = base + tid;
        int f = (j < NN) ? g_sel[j] : 0;
        int xv = f;
        #pragma unroll
        for (int o = 1; o < 32; o <<= 1) {
            int y = __shfl_up_sync(0xffffffffu, xv, o);
            if (lane >= o) xv += y;
        }
        if (lane == 31) wsum[wid] = xv;
        __syncthreads();
        int woff = 0;
        #pragma unroll
        for (int w = 0; w < 8; w++) if (w < wid) woff += wsum[w];
        int incl = xv + woff;
        int pos = carry + incl - f;
        if (j < NN) {
            g_epos[j] = pos;
            if (f) {
                g_idx[pos] = j;
                out[IDX_OFF + pos] = (float)j;
            }
        }
        __syncthreads();
        if (tid == 255) carry += incl;
        __syncthreads();
    }
}

// ---------------- 8) x_pool gather ----------------
__global__ __launch_bounds__(128) void gather_x_kernel(float* __restrict__ out) {
    int r = blockIdx.x;
    int d = threadIdx.x;
    int ir = g_idx[r];
    out[XP_OFF + (size_t)r * DD + d] = g_h[(size_t)ir * DD + d];
}

// ---------------- 9) adjacency/motif pool gathers (smem-staged, coalesced DRAM reads) ----------------
__global__ __launch_bounds__(256) void gather_pools_kernel(const float* __restrict__ adj,
                                                           const float* __restrict__ motif,
                                                           float* __restrict__ out) {
    __shared__ float smA[CI];
    __shared__ float smM[CI];
    __shared__ int scr[2];
    int tid = threadIdx.x;
    int r = blockIdx.x;
    int ir = g_idx[r];
    const float* arow = adj   + (size_t)ir * NN;
    const float* mrow = motif + (size_t)ir * NN;
    float* oa = out + ADJ_OFF + (size_t)r * KSEL;
    float* om = out + MOT_OFF + (size_t)r * KSEL;

    for (int q0 = 0; q0 < NN; q0 += CI) {
        int qn = min(CI, NN - q0);
        for (int f = tid * 4; f < qn; f += 1024) {
            *(float4*)&smA[f] = *(const float4*)&arow[q0 + f];
            *(float4*)&smM[f] = *(const float4*)&mrow[q0 + f];
        }
        if (tid == 0) {
            scr[0] = g_epos[q0];
            scr[1] = (q0 + CI < NN) ? g_epos[q0 + CI] : KSEL;
        }
        __syncthreads();
        int c0 = scr[0], c1 = scr[1];
        for (int c = c0 + tid; c < c1; c += 256) {
            int ic = g_idx[c] - q0;
            oa[c] = smA[ic];
            om[c] = smM[ic];
        }
        __syncthreads();
    }
}

// ---------------- launch ----------------
extern "C" void kernel_launch(void* const* d_in, const int* in_sizes, int n_in,
                              void* d_out, int out_size) {
    const float* x       = (const float*)d_in[0];
    const float* adj     = (const float*)d_in[1];
    const float* motif   = (const float*)d_in[2];
    const float* W       = (const float*)d_in[3];
    const float* b_gcn   = (const float*)d_in[4];
    const float* w_score = (const float*)d_in[5];
    const float* b_score = (const float*)d_in[6];
    float* out = (float*)d_out;

    colsum_kernel<<<dim3((NN + 255) / 256, NPART), 256>>>(motif);
    dinv_kernel<<<(NN + 255) / 256, 256>>>();
    compute_P_kernel<<<NN / 16, 128>>>(x, W);
    hmma_gemm_kernel<<<dim3(NJT, NSPLIT), 128, 49152>>>(motif);
    epilogue_kernel<<<NN, 128>>>(b_gcn, w_score, b_score, out);
    topk_rank_kernel<<<(NN + 255) / 256, 256>>>();
    compact_kernel<<<1, 256>>>(out);
    gather_x_kernel<<<KSEL, 128>>>(out);
    gather_pools_kernel<<<KSEL, 256>>>(adj, motif, out);
}

// round 16
// speedup vs baseline: 1.8303x; 1.0347x over previous
#include <cuda_runtime.h>
#include <cuda_bf16.h>
#include <cstdint>
#include <math.h>

#define NN 10000
#define DD 128
#define KSEL 5000
#define BM 128
#define BK 32
#define NST 313                 // ceil(10000/32) k-stages total
#define NKPAD (NST * BK)        // 10016 padded k rows (for B only)
#define NSPLIT 15
#define NJT 79                  // j tiles of 128
#define CI 2048                 // gather chunk
#define NPART 20                // colsum i-parts (500 rows each)

// d_out layout (float32): x_pool[5000*128] | adj_pool[5000*5000] | motif_pool[5000*5000] | scores[10000] | top_idx[5000]
#define XP_OFF   0LL
#define ADJ_OFF  640000LL
#define MOT_OFF  (640000LL + 25000000LL)
#define SC_OFF   (640000LL + 50000000LL)
#define IDX_OFF  (SC_OFF + 10000LL)

// ---------------- scratch (device globals; zero-initialized at load; pads never written) ----------------
__device__ float g_colpart[NPART][NN];
__device__ float g_dinv[NN];
__device__ float g_P[(size_t)NN * DD];                 // dinv_i * (x @ W^T), fp32
__device__ __nv_bfloat16 g_Pbh[(size_t)NKPAD * DD];    // P bf16 hi, [i][d], rows >= NN stay zero
__device__ __nv_bfloat16 g_Pbl[(size_t)NKPAD * DD];    // P bf16 lo
__device__ float g_Gpart[NSPLIT][(size_t)NN * DD];     // split-K partials
__device__ float g_h[(size_t)NN * DD];
__device__ float g_scores[NN];
__device__ int   g_sel[NN];
__device__ int   g_epos[NN];                           // exclusive scan of g_sel
__device__ int   g_idx[KSEL];

// ---------------- PTX helpers (sm_80-level; compile on compute_103 family target) ----------------
__device__ __forceinline__ uint32_t smem_u32(const void* p) {
    uint32_t a;
    asm("{ .reg .u64 t; cvta.to.shared.u64 t, %1; cvt.u32.u64 %0, t; }" : "=r"(a) : "l"(p));
    return a;
}
__device__ __forceinline__ void cpasync16(uint32_t dst, const void* src) {
    asm volatile("cp.async.cg.shared.global [%0], [%1], 16;" :: "r"(dst), "l"(src));
}
#define CP_COMMIT() asm volatile("cp.async.commit_group;" ::: "memory")
#define CP_WAIT(n)  asm volatile("cp.async.wait_group %0;" :: "n"(n) : "memory")

__device__ __forceinline__ void sts64(uint32_t addr, uint2 v) {
    asm volatile("st.shared.v2.b32 [%0], {%1,%2};" :: "r"(addr), "r"(v.x), "r"(v.y));
}
__device__ __forceinline__ void ldsm4t(uint32_t* r, uint32_t addr) {
    asm volatile("ldmatrix.sync.aligned.m8n8.x4.trans.shared.b16 {%0,%1,%2,%3}, [%4];"
        : "=r"(r[0]), "=r"(r[1]), "=r"(r[2]), "=r"(r[3]) : "r"(addr));
}
__device__ __forceinline__ void mma16816(float* c, const uint32_t* a, const uint32_t* b) {
    asm volatile("mma.sync.aligned.m16n8k16.row.col.f32.bf16.bf16.f32 "
        "{%0,%1,%2,%3}, {%4,%5,%6,%7}, {%8,%9}, {%0,%1,%2,%3};"
        : "+f"(c[0]), "+f"(c[1]), "+f"(c[2]), "+f"(c[3])
        : "r"(a[0]), "r"(a[1]), "r"(a[2]), "r"(a[3]), "r"(b[0]), "r"(b[1]));
}

// ---------------- 1) column partial sums of motif (coalesced, full-chip) ----------------
__global__ __launch_bounds__(256) void colsum_kernel(const float* __restrict__ motif) {
    int j = blockIdx.x * 256 + threadIdx.x;
    if (j >= NN) return;
    int part = blockIdx.y;
    int r0 = part * (NN / NPART);
    int r1 = r0 + (NN / NPART);
    float s0 = 0.f, s1 = 0.f, s2 = 0.f, s3 = 0.f;
    for (int i = r0; i < r1; i += 4) {
        s0 += motif[(size_t)(i + 0) * NN + j];
        s1 += motif[(size_t)(i + 1) * NN + j];
        s2 += motif[(size_t)(i + 2) * NN + j];
        s3 += motif[(size_t)(i + 3) * NN + j];
    }
    g_colpart[part][j] = (s0 + s1) + (s2 + s3);
}

// ---------------- 2) deg -> dinv ----------------
__global__ __launch_bounds__(256) void dinv_kernel() {
    int j = blockIdx.x * 256 + threadIdx.x;
    if (j >= NN) return;
    float d = 1.0f;  // +I diagonal
    #pragma unroll
    for (int p = 0; p < NPART; p++) d += g_colpart[p][j];
    g_dinv[j] = 1.0f / sqrtf(d);
}

// ---------------- 3) P[i,d] = dinv[i]*(x@W^T); also emit bf16 hi/lo in [i][d] ----------------
__global__ __launch_bounds__(128) void compute_P_kernel(const float* __restrict__ x,
                                                        const float* __restrict__ W) {
    __shared__ float smX[16][128];
    int tid = threadIdx.x;   // = d
    int i0 = blockIdx.x * 16;
    for (int f = tid; f < 16 * 32; f += 128) {
        int r = f >> 5, c = (f & 31) * 4;
        *(float4*)&smX[r][c] = *(const float4*)&x[(size_t)(i0 + r) * DD + c];
    }
    __syncthreads();
    float acc[16];
    #pragma unroll
    for (int r = 0; r < 16; r++) acc[r] = 0.f;
    const float* wrow = W + (size_t)tid * DD;
    for (int e = 0; e < DD; e += 4) {
        float4 w4 = *(const float4*)&wrow[e];
        #pragma unroll
        for (int r = 0; r < 16; r++) {
            float4 x4 = *(const float4*)&smX[r][e];
            acc[r] += x4.x * w4.x + x4.y * w4.y + x4.z * w4.z + x4.w * w4.w;
        }
    }
    #pragma unroll
    for (int r = 0; r < 16; r++) {
        int gi = i0 + r;
        float p = g_dinv[gi] * acc[r];
        g_P[(size_t)gi * DD + tid] = p;
        __nv_bfloat16 hb = __float2bfloat16(p);
        g_Pbh[(size_t)gi * DD + tid] = hb;
        g_Pbl[(size_t)gi * DD + tid] = __float2bfloat16(p - __bfloat162float(hb));
    }
}

// ---------------- 4) HMMA GEMM: G[j,d] = sum_i motif[i,j]*P[i,d], bf16 hi/lo x3 ----------------
// 128 threads, warp grid 2x2, warp tile 64m x 64n over BM=128 x BN=128.
// A from fp32 motif (interleaved coalesced LDG, convert in regs, swizzled STS.64).
// B pre-split bf16 via cp.async. 2-deep smem pipeline, 64KB dyn smem.
__global__ __launch_bounds__(128, 2) void hmma_gemm_kernel(const float* __restrict__ motif) {
    extern __shared__ __align__(128) char dynsm[];
    const uint32_t smbase = smem_u32(dynsm);
    const uint32_t A_h = smbase;             // [2][32][256B] : 2 x 8192
    const uint32_t A_l = smbase + 16384;
    const uint32_t B_h = smbase + 32768;     // [2][32][256B] : 2 x 8192
    const uint32_t B_l = smbase + 49152;     // total 65536B

    const int tid = threadIdx.x;
    const int lane = tid & 31;
    const int wid = tid >> 5;
    const int wm = wid & 1;      // 2 warp-rows (m: 64 each)
    const int wn = wid >> 1;     // 2 warp-cols (n: 64 each)
    const int j0 = blockIdx.x * BM;
    const int split = blockIdx.y;
    const int sbeg = (split * NST) / NSPLIT;
    const int ns = ((split + 1) * NST) / NSPLIT - sbeg;

    // A loader: akr = k-row (4 threads/row), aq selects interleaved float4s p = f*4 + aq
    const int akr = tid >> 2;
    const int aq = tid & 3;
    bool av[8];
    #pragma unroll
    for (int f = 0; f < 8; f++) av[f] = (j0 + f * 16 + aq * 4) < NN;   // NN%4==0
    const float* aSrcBase = motif + (size_t)j0 + (size_t)aq * 4;
    uint32_t aAd[8];
    #pragma unroll
    for (int f = 0; f < 8; f++) {
        uint32_t c = (uint32_t)(f * 2 + (aq >> 1));
        aAd[f] = (uint32_t)akr * 256u + (((c & 8u) | ((c ^ ((uint32_t)akr & 7u)) & 7u)) * 16u)
               + (uint32_t)(aq & 1) * 8u;
    }

    // B loader: bk = k-row (4 threads/row), 4 chunks of 16B per matrix
    const int bk = tid >> 2;
    const int bq = tid & 3;
    uint32_t bOff[4];
    #pragma unroll
    for (int e = 0; e < 4; e++) {
        uint32_t c = (uint32_t)(bq * 4 + e);
        bOff[e] = (uint32_t)bk * 256 + (((c & 8u) | ((c ^ (uint32_t)(bk & 7)) & 7u)) * 16);
    }
    const __nv_bfloat16* bSrcH = g_Pbh + (size_t)bk * DD + bq * 32;
    const __nv_bfloat16* bSrcL = g_Pbl + (size_t)bk * DD + bq * 32;

    float4 areg[8];
    float acc[4][8][4];
    #pragma unroll
    for (int mt = 0; mt < 4; mt++)
        #pragma unroll
        for (int nt = 0; nt < 8; nt++)
            #pragma unroll
            for (int q = 0; q < 4; q++) acc[mt][nt][q] = 0.f;

    const float4 z4 = make_float4(0.f, 0.f, 0.f, 0.f);

#define LDG_A(t) do { \
    int _i = (sbeg + (t)) * BK + akr; \
    bool _r = (_i < NN); \
    const float* _p = aSrcBase + (size_t)_i * NN; \
    _Pragma("unroll") \
    for (int _f = 0; _f < 8; _f++) \
        areg[_f] = (_r && av[_f]) ? *(const float4*)(_p + _f * 16) : z4; \
} while (0)

#define STS_A(t) do { \
    uint32_t _bo = ((t) & 1) * 8192u; \
    _Pragma("unroll") \
    for (int _f = 0; _f < 8; _f++) { \
        float4 _v = areg[_f]; \
        __nv_bfloat162 _h0 = __floats2bfloat162_rn(_v.x, _v.y); \
        __nv_bfloat162 _h1 = __floats2bfloat162_rn(_v.z, _v.w); \
        __nv_bfloat162 _l0 = __floats2bfloat162_rn(_v.x - __bfloat162float(_h0.x), \
                                                   _v.y - __bfloat162float(_h0.y)); \
        __nv_bfloat162 _l1 = __floats2bfloat162_rn(_v.z - __bfloat162float(_h1.x), \
                                                   _v.w - __bfloat162float(_h1.y)); \
        sts64(A_h + _bo + aAd[_f], make_uint2(*(uint32_t*)&_h0, *(uint32_t*)&_h1)); \
        sts64(A_l + _bo + aAd[_f], make_uint2(*(uint32_t*)&_l0, *(uint32_t*)&_l1)); \
    } \
} while (0)

#define CP_B(t) do { \
    size_t _k = (size_t)(sbeg + (t)) * BK * DD; \
    uint32_t _bb = ((t) & 1) * 8192u; \
    _Pragma("unroll") \
    for (int _e = 0; _e < 4; _e++) { \
        cpasync16(B_h + _bb + bOff[_e], bSrcH + _k + _e * 8); \
        cpasync16(B_l + _bb + bOff[_e], bSrcL + _k + _e * 8); \
    } \
    CP_COMMIT(); \
} while (0)

    // prologue
    LDG_A(0); CP_B(0); STS_A(0);
    LDG_A(1); CP_B(1);

    for (int t = 0; t < ns; t++) {
        const int b = t & 1;
        if (t + 1 < ns) STS_A(t + 1);
        if (t + 1 < ns) { CP_WAIT(1); } else { CP_WAIT(0); }
        __syncthreads();
        if (t + 2 < ns) LDG_A(t + 2);

        const uint32_t Ah = A_h + b * 8192u, Al = A_l + b * 8192u;
        const uint32_t Bh = B_h + b * 8192u, Bl = B_l + b * 8192u;
        #pragma unroll
        for (int kb = 0; kb < 2; kb++) {
            uint32_t ah[4][4], al[4][4];
            const int krA = kb * 16 + (lane & 7) + ((lane & 16) ? 8 : 0);
            #pragma unroll
            for (int mt = 0; mt < 4; mt++) {
                uint32_t c = (uint32_t)(wm * 8 + mt * 2 + ((lane & 8) ? 1 : 0));
                uint32_t ad = (uint32_t)krA * 256 + (((c & 8u) | ((c ^ (uint32_t)(krA & 7)) & 7u)) * 16);
                ldsm4t(ah[mt], Ah + ad);
                ldsm4t(al[mt], Al + ad);
            }
            const int krB = kb * 16 + (lane & 7) + ((lane & 8) ? 8 : 0);
            #pragma unroll
            for (int np = 0; np < 4; np++) {
                uint32_t c = (uint32_t)(wn * 8 + np * 2 + ((lane & 16) ? 1 : 0));
                uint32_t bd = (uint32_t)krB * 256 + (((c & 8u) | ((c ^ (uint32_t)(krB & 7)) & 7u)) * 16);
                uint32_t bh[4], bl[4];
                ldsm4t(bh, Bh + bd);
                ldsm4t(bl, Bl + bd);
                #pragma unroll
                for (int mt = 0; mt < 4; mt++)
                    #pragma unroll
                    for (int hf = 0; hf < 2; hf++) {
                        const int nt = np * 2 + hf;
                        uint32_t bhp[2] = {bh[hf * 2], bh[hf * 2 + 1]};
                        uint32_t blp[2] = {bl[hf * 2], bl[hf * 2 + 1]};
                        mma16816(acc[mt][nt], ah[mt], bhp);   // hi*hi
                        mma16816(acc[mt][nt], ah[mt], blp);   // hi*lo
                        mma16816(acc[mt][nt], al[mt], bhp);   // lo*hi
                    }
            }
        }
        __syncthreads();
        if (t + 2 < ns) CP_B(t + 2);
    }
#undef LDG_A
#undef STS_A
#undef CP_B

    // store partial G
    float* G = g_Gpart[split];
    #pragma unroll
    for (int mt = 0; mt < 4; mt++)
        #pragma unroll
        for (int nt = 0; nt < 8; nt++) {
            int j = j0 + wm * 64 + mt * 16 + (lane >> 2);
            int d = wn * 64 + nt * 8 + (lane & 3) * 2;
            if (j < NN) {
                float2 v = make_float2(acc[mt][nt][0], acc[mt][nt][1]);
                *(float2*)(G + (size_t)j * DD + d) = v;
            }
            if (j + 8 < NN) {
                float2 v = make_float2(acc[mt][nt][2], acc[mt][nt][3]);
                *(float2*)(G + (size_t)(j + 8) * DD + d) = v;
            }
        }
}

// ---------------- 5) h = tanh(dinv_j*(sum G + P_j) + b); scores ----------------
__global__ __launch_bounds__(128) void epilogue_kernel(const float* __restrict__ b_gcn,
                                                       const float* __restrict__ w_score,
                                                       const float* __restrict__ b_score,
                                                       float* __restrict__ out) {
    int j = blockIdx.x;
    int d = threadIdx.x;
    size_t o = (size_t)j * DD + d;
    float g = g_P[o];
    #pragma unroll
    for (int s = 0; s < NSPLIT; s++) g += g_Gpart[s][o];
    float hv = tanhf(g_dinv[j] * g + b_gcn[d]);
    g_h[o] = hv;
    float v = hv * w_score[d];
    #pragma unroll
    for (int off = 16; off > 0; off >>= 1) v += __shfl_down_sync(0xffffffffu, v, off);
    __shared__ float ws[4];
    if ((d & 31) == 0) ws[d >> 5] = v;
    __syncthreads();
    if (d == 0) {
        float sc = ((ws[0] + ws[1]) + (ws[2] + ws[3])) + b_score[0];
        g_scores[j] = sc;
        out[SC_OFF + j] = sc;
    }
}

// ---------------- 6) top-k via exact rank (matches lax.top_k stable ties) ----------------
__global__ __launch_bounds__(256) void topk_rank_kernel() {
    __shared__ float ss[NN];
    int tid = threadIdx.x;
    for (int f = tid; f < NN; f += 256) ss[f] = g_scores[f];
    __syncthreads();
    int j = blockIdx.x * 256 + tid;
    if (j >= NN) return;
    float sj = ss[j];
    int rank = 0;
    for (int i = 0; i < NN; i++) {
        float si = ss[i];
        rank += (si > sj) ? 1 : ((si == sj && i < j) ? 1 : 0);
    }
    g_sel[j] = (rank < KSEL) ? 1 : 0;
}

// ---------------- 7) compact selected indices (ascending) + exclusive scan ----------------
__global__ __launch_bounds__(256) void compact_kernel(float* __restrict__ out) {
    __shared__ int wsum[8];
    __shared__ int carry;
    int tid = threadIdx.x, lane = tid & 31, wid = tid >> 5;
    if (tid == 0) carry = 0;
    __syncthreads();
    for (int base = 0; base < NN; base += 256) {
        int j = base + tid;
        int f = (j < NN) ? g_sel[j] : 0;
        int xv = f;
        #pragma unroll
        for (int o = 1; o < 32; o <<= 1) {
            int y = __shfl_up_sync(0xffffffffu, xv, o);
            if (lane >= o) xv += y;
        }
        if (lane == 31) wsum[wid] = xv;
        __syncthreads();
        int woff = 0;
        #pragma unroll
        for (int w = 0; w < 8; w++) if (w < wid) woff += wsum[w];
        int incl = xv + woff;
        int pos = carry + incl - f;
        if (j < NN) {
            g_epos[j] = pos;
            if (f) {
                g_idx[pos] = j;
                out[IDX_OFF + pos] = (float)j;
            }
        }
        __syncthreads();
        if (tid == 255) carry += incl;
        __syncthreads();
    }
}

// ---------------- 8) x_pool gather ----------------
__global__ __launch_bounds__(128) void gather_x_kernel(float* __restrict__ out) {
    int r = blockIdx.x;
    int d = threadIdx.x;
    int ir = g_idx[r];
    out[XP_OFF + (size_t)r * DD + d] = g_h[(size_t)ir * DD + d];
}

// ---------------- 9) adjacency/motif pool gathers (smem-staged, coalesced DRAM reads) ----------------
__global__ __launch_bounds__(256) void gather_pools_kernel(const float* __restrict__ adj,
                                                           const float* __restrict__ motif,
                                                           float* __restrict__ out) {
    __shared__ float smA[CI];
    __shared__ float smM[CI];
    __shared__ int scr[2];
    int tid = threadIdx.x;
    int r = blockIdx.x;
    int ir = g_idx[r];
    const float* arow = adj   + (size_t)ir * NN;
    const float* mrow = motif + (size_t)ir * NN;
    float* oa = out + ADJ_OFF + (size_t)r * KSEL;
    float* om = out + MOT_OFF + (size_t)r * KSEL;

    for (int q0 = 0; q0 < NN; q0 += CI) {
        int qn = min(CI, NN - q0);
        for (int f = tid * 4; f < qn; f += 1024) {
            *(float4*)&smA[f] = *(const float4*)&arow[q0 + f];
            *(float4*)&smM[f] = *(const float4*)&mrow[q0 + f];
        }
        if (tid == 0) {
            scr[0] = g_epos[q0];
            scr[1] = (q0 + CI < NN) ? g_epos[q0 + CI] : KSEL;
        }
        __syncthreads();
        int c0 = scr[0], c1 = scr[1];
        for (int c = c0 + tid; c < c1; c += 256) {
            int ic = g_idx[c] - q0;
            oa[c] = smA[ic];
            om[c] = smM[ic];
        }
        __syncthreads();
    }
}

// ---------------- launch ----------------
extern "C" void kernel_launch(void* const* d_in, const int* in_sizes, int n_in,
                              void* d_out, int out_size) {
    const float* x       = (const float*)d_in[0];
    const float* adj     = (const float*)d_in[1];
    const float* motif   = (const float*)d_in[2];
    const float* W       = (const float*)d_in[3];
    const float* b_gcn   = (const float*)d_in[4];
    const float* w_score = (const float*)d_in[5];
    const float* b_score = (const float*)d_in[6];
    float* out = (float*)d_out;

    cudaFuncSetAttribute(hmma_gemm_kernel, cudaFuncAttributeMaxDynamicSharedMemorySize, 65536);

    colsum_kernel<<<dim3((NN + 255) / 256, NPART), 256>>>(motif);
    dinv_kernel<<<(NN + 255) / 256, 256>>>();
    compute_P_kernel<<<NN / 16, 128>>>(x, W);
    hmma_gemm_kernel<<<dim3(NJT, NSPLIT), 128, 65536>>>(motif);
    epilogue_kernel<<<NN, 128>>>(b_gcn, w_score, b_score, out);
    topk_rank_kernel<<<(NN + 255) / 256, 256>>>();
    compact_kernel<<<1, 256>>>(out);
    gather_x_kernel<<<KSEL, 128>>>(out);
    gather_pools_kernel<<<KSEL, 256>>>(adj, motif, out);
}

// round 17
// speedup vs baseline: 1.9085x; 1.0427x over previous
#include <cuda_runtime.h>
#include <cuda_bf16.h>
#include <cstdint>
#include <math.h>

#define NN 10000
#define DD 128
#define KSEL 5000
#define BM 128
#define BK 32
#define NST 313                 // ceil(10000/32) k-stages total
#define NKPAD (NST * BK)        // 10016 padded k rows (for B only)
#define NSPLIT 15
#define NJT 79                  // j tiles of 128
#define CI 2048                 // gather chunk
#define NPART 20                // colsum i-parts (500 rows each)

// d_out layout (float32): x_pool[5000*128] | adj_pool[5000*5000] | motif_pool[5000*5000] | scores[10000] | top_idx[5000]
#define XP_OFF   0LL
#define ADJ_OFF  640000LL
#define MOT_OFF  (640000LL + 25000000LL)
#define SC_OFF   (640000LL + 50000000LL)
#define IDX_OFF  (SC_OFF + 10000LL)

// ---------------- scratch (device globals; zero-initialized at load; pads never written) ----------------
__device__ float g_colpart[NPART][NN];
__device__ float g_dinv[NN];
__device__ float g_P[(size_t)NN * DD];                 // dinv_i * (x @ W^T), fp32
__device__ __nv_bfloat16 g_Pbh[(size_t)NKPAD * DD];    // P bf16 hi, [i][d], rows >= NN stay zero
__device__ __nv_bfloat16 g_Pbl[(size_t)NKPAD * DD];    // P bf16 lo
__device__ float g_Gpart[NSPLIT][(size_t)NN * DD];     // split-K partials
__device__ float g_h[(size_t)NN * DD];
__device__ float g_scores[NN];
__device__ int   g_sel[NN];
__device__ int   g_epos[NN];                           // exclusive scan of g_sel
__device__ int   g_idx[KSEL];

// ---------------- PTX helpers (sm_80-level; compile on compute_103 family target) ----------------
__device__ __forceinline__ uint32_t smem_u32(const void* p) {
    uint32_t a;
    asm("{ .reg .u64 t; cvta.to.shared.u64 t, %1; cvt.u32.u64 %0, t; }" : "=r"(a) : "l"(p));
    return a;
}
__device__ __forceinline__ void cpasync16(uint32_t dst, const void* src) {
    asm volatile("cp.async.cg.shared.global [%0], [%1], 16;" :: "r"(dst), "l"(src));
}
#define CP_COMMIT() asm volatile("cp.async.commit_group;" ::: "memory")
#define CP_WAIT(n)  asm volatile("cp.async.wait_group %0;" :: "n"(n) : "memory")

__device__ __forceinline__ void sts64(uint32_t addr, uint2 v) {
    asm volatile("st.shared.v2.b32 [%0], {%1,%2};" :: "r"(addr), "r"(v.x), "r"(v.y));
}
__device__ __forceinline__ void ldsm4t(uint32_t* r, uint32_t addr) {
    asm volatile("ldmatrix.sync.aligned.m8n8.x4.trans.shared.b16 {%0,%1,%2,%3}, [%4];"
        : "=r"(r[0]), "=r"(r[1]), "=r"(r[2]), "=r"(r[3]) : "r"(addr));
}
__device__ __forceinline__ void mma16816(float* c, const uint32_t* a, const uint32_t* b) {
    asm volatile("mma.sync.aligned.m16n8k16.row.col.f32.bf16.bf16.f32 "
        "{%0,%1,%2,%3}, {%4,%5,%6,%7}, {%8,%9}, {%0,%1,%2,%3};"
        : "+f"(c[0]), "+f"(c[1]), "+f"(c[2]), "+f"(c[3])
        : "r"(a[0]), "r"(a[1]), "r"(a[2]), "r"(a[3]), "r"(b[0]), "r"(b[1]));
}

// ---------------- 1) column partial sums of motif (coalesced, full-chip) ----------------
__global__ __launch_bounds__(256) void colsum_kernel(const float* __restrict__ motif) {
    int j = blockIdx.x * 256 + threadIdx.x;
    if (j >= NN) return;
    int part = blockIdx.y;
    int r0 = part * (NN / NPART);
    int r1 = r0 + (NN / NPART);
    float s0 = 0.f, s1 = 0.f, s2 = 0.f, s3 = 0.f;
    for (int i = r0; i < r1; i += 4) {
        s0 += motif[(size_t)(i + 0) * NN + j];
        s1 += motif[(size_t)(i + 1) * NN + j];
        s2 += motif[(size_t)(i + 2) * NN + j];
        s3 += motif[(size_t)(i + 3) * NN + j];
    }
    g_colpart[part][j] = (s0 + s1) + (s2 + s3);
}

// ---------------- 2) deg -> dinv ----------------
__global__ __launch_bounds__(256) void dinv_kernel() {
    int j = blockIdx.x * 256 + threadIdx.x;
    if (j >= NN) return;
    float d = 1.0f;  // +I diagonal
    #pragma unroll
    for (int p = 0; p < NPART; p++) d += g_colpart[p][j];
    g_dinv[j] = 1.0f / sqrtf(d);
}

// ---------------- 3) P[i,d] = dinv[i]*(x@W^T); also emit bf16 hi/lo in [i][d] ----------------
__global__ __launch_bounds__(128) void compute_P_kernel(const float* __restrict__ x,
                                                        const float* __restrict__ W) {
    __shared__ float smX[16][128];
    int tid = threadIdx.x;   // = d
    int i0 = blockIdx.x * 16;
    for (int f = tid; f < 16 * 32; f += 128) {
        int r = f >> 5, c = (f & 31) * 4;
        *(float4*)&smX[r][c] = *(const float4*)&x[(size_t)(i0 + r) * DD + c];
    }
    __syncthreads();
    float acc[16];
    #pragma unroll
    for (int r = 0; r < 16; r++) acc[r] = 0.f;
    const float* wrow = W + (size_t)tid * DD;
    for (int e = 0; e < DD; e += 4) {
        float4 w4 = *(const float4*)&wrow[e];
        #pragma unroll
        for (int r = 0; r < 16; r++) {
            float4 x4 = *(const float4*)&smX[r][e];
            acc[r] += x4.x * w4.x + x4.y * w4.y + x4.z * w4.z + x4.w * w4.w;
        }
    }
    #pragma unroll
    for (int r = 0; r < 16; r++) {
        int gi = i0 + r;
        float p = g_dinv[gi] * acc[r];
        g_P[(size_t)gi * DD + tid] = p;
        __nv_bfloat16 hb = __float2bfloat16(p);
        g_Pbh[(size_t)gi * DD + tid] = hb;
        g_Pbl[(size_t)gi * DD + tid] = __float2bfloat16(p - __bfloat162float(hb));
    }
}

// ---------------- 4) HMMA GEMM: G[j,d] = sum_i motif[i,j]*P[i,d], bf16 hi/lo x3 ----------------
// 256 threads, warp grid 4m x 2n, warp tile 32m x 64n over BM=128 x BN=128.
// A from fp32 motif (coalesced LDG, convert in regs, swizzled STS.64).
// B pre-split bf16 via cp.async. 2-deep smem pipeline, 64KB dyn smem, 2 CTAs/SM.
__global__ __launch_bounds__(256, 2) void hmma_gemm_kernel(const float* __restrict__ motif) {
    extern __shared__ __align__(128) char dynsm[];
    const uint32_t smbase = smem_u32(dynsm);
    const uint32_t A_h = smbase;             // [2][32][256B] : 2 x 8192
    const uint32_t A_l = smbase + 16384;
    const uint32_t B_h = smbase + 32768;     // [2][32][256B] : 2 x 8192
    const uint32_t B_l = smbase + 49152;     // total 65536B

    const int tid = threadIdx.x;
    const int lane = tid & 31;
    const int wid = tid >> 5;
    const int wm = wid & 3;      // 4 warp-rows (m: 32 each)
    const int wn = wid >> 2;     // 2 warp-cols (n: 64 each)
    const int j0 = blockIdx.x * BM;
    const int split = blockIdx.y;
    const int sbeg = (split * NST) / NSPLIT;
    const int ns = ((split + 1) * NST) / NSPLIT - sbeg;

    // A loader: akr = k-row (8 threads/row), aq picks 4 interleaved float4s j = aq*4 + f*32
    const int akr = tid >> 3;
    const int aq = tid & 7;
    bool av[4];
    #pragma unroll
    for (int f = 0; f < 4; f++) av[f] = (j0 + aq * 4 + f * 32) < NN;   // NN%4==0
    const float* aSrcBase = motif + (size_t)j0 + (size_t)aq * 4;
    uint32_t aAd[4];
    #pragma unroll
    for (int f = 0; f < 4; f++) {
        uint32_t c = (uint32_t)((aq >> 1) + f * 4);    // byte off (aq*8 + f*64)/16
        aAd[f] = (uint32_t)akr * 256u + (((c & 8u) | ((c ^ ((uint32_t)akr & 7u)) & 7u)) * 16u)
               + (uint32_t)(aq & 1) * 8u;
    }

    // B loader: bk = k-row (8 threads/row), 2 chunks of 16B per matrix
    const int bk = tid >> 3;
    const int bq = tid & 7;
    uint32_t bOff[2];
    #pragma unroll
    for (int e = 0; e < 2; e++) {
        uint32_t c = (uint32_t)(bq * 2 + e);
        bOff[e] = (uint32_t)bk * 256 + (((c & 8u) | ((c ^ (uint32_t)(bk & 7)) & 7u)) * 16);
    }
    const __nv_bfloat16* bSrcH = g_Pbh + (size_t)bk * DD + bq * 16;
    const __nv_bfloat16* bSrcL = g_Pbl + (size_t)bk * DD + bq * 16;

    float4 areg[4];
    float acc[2][8][4];
    #pragma unroll
    for (int mt = 0; mt < 2; mt++)
        #pragma unroll
        for (int nt = 0; nt < 8; nt++)
            #pragma unroll
            for (int q = 0; q < 4; q++) acc[mt][nt][q] = 0.f;

    const float4 z4 = make_float4(0.f, 0.f, 0.f, 0.f);

#define LDG_A(t) do { \
    int _i = (sbeg + (t)) * BK + akr; \
    bool _r = (_i < NN); \
    const float* _p = aSrcBase + (size_t)_i * NN; \
    _Pragma("unroll") \
    for (int _f = 0; _f < 4; _f++) \
        areg[_f] = (_r && av[_f]) ? *(const float4*)(_p + _f * 32) : z4; \
} while (0)

#define STS_A(t) do { \
    uint32_t _bo = ((t) & 1) * 8192u; \
    _Pragma("unroll") \
    for (int _f = 0; _f < 4; _f++) { \
        float4 _v = areg[_f]; \
        __nv_bfloat162 _h0 = __floats2bfloat162_rn(_v.x, _v.y); \
        __nv_bfloat162 _h1 = __floats2bfloat162_rn(_v.z, _v.w); \
        __nv_bfloat162 _l0 = __floats2bfloat162_rn(_v.x - __bfloat162float(_h0.x), \
                                                   _v.y - __bfloat162float(_h0.y)); \
        __nv_bfloat162 _l1 = __floats2bfloat162_rn(_v.z - __bfloat162float(_h1.x), \
                                                   _v.w - __bfloat162float(_h1.y)); \
        sts64(A_h + _bo + aAd[_f], make_uint2(*(uint32_t*)&_h0, *(uint32_t*)&_h1)); \
        sts64(A_l + _bo + aAd[_f], make_uint2(*(uint32_t*)&_l0, *(uint32_t*)&_l1)); \
    } \
} while (0)

#define CP_B(t) do { \
    size_t _k = (size_t)(sbeg + (t)) * BK * DD; \
    uint32_t _bb = ((t) & 1) * 8192u; \
    _Pragma("unroll") \
    for (int _e = 0; _e < 2; _e++) { \
        cpasync16(B_h + _bb + bOff[_e], bSrcH + _k + _e * 8); \
        cpasync16(B_l + _bb + bOff[_e], bSrcL + _k + _e * 8); \
    } \
    CP_COMMIT(); \
} while (0)

    // prologue
    LDG_A(0); CP_B(0); STS_A(0);
    LDG_A(1); CP_B(1);

    for (int t = 0; t < ns; t++) {
        const int b = t & 1;
        if (t + 1 < ns) STS_A(t + 1);
        if (t + 1 < ns) { CP_WAIT(1); } else { CP_WAIT(0); }
        __syncthreads();
        if (t + 2 < ns) LDG_A(t + 2);

        const uint32_t Ah = A_h + b * 8192u, Al = A_l + b * 8192u;
        const uint32_t Bh = B_h + b * 8192u, Bl = B_l + b * 8192u;
        #pragma unroll
        for (int kb = 0; kb < 2; kb++) {
            uint32_t ah[2][4], al[2][4];
            const int krA = kb * 16 + (lane & 7) + ((lane & 16) ? 8 : 0);
            #pragma unroll
            for (int mt = 0; mt < 2; mt++) {
                uint32_t c = (uint32_t)(wm * 4 + mt * 2 + ((lane & 8) ? 1 : 0));
                uint32_t ad = (uint32_t)krA * 256 + (((c & 8u) | ((c ^ (uint32_t)(krA & 7)) & 7u)) * 16);
                ldsm4t(ah[mt], Ah + ad);
                ldsm4t(al[mt], Al + ad);
            }
            const int krB = kb * 16 + (lane & 7) + ((lane & 8) ? 8 : 0);
            #pragma unroll
            for (int np = 0; np < 4; np++) {
                uint32_t c = (uint32_t)(wn * 8 + np * 2 + ((lane & 16) ? 1 : 0));
                uint32_t bd = (uint32_t)krB * 256 + (((c & 8u) | ((c ^ (uint32_t)(krB & 7)) & 7u)) * 16);
                uint32_t bh[4], bl[4];
                ldsm4t(bh, Bh + bd);
                ldsm4t(bl, Bl + bd);
                #pragma unroll
                for (int mt = 0; mt < 2; mt++)
                    #pragma unroll
                    for (int hf = 0; hf < 2; hf++) {
                        const int nt = np * 2 + hf;
                        uint32_t bhp[2] = {bh[hf * 2], bh[hf * 2 + 1]};
                        uint32_t blp[2] = {bl[hf * 2], bl[hf * 2 + 1]};
                        mma16816(acc[mt][nt], ah[mt], bhp);   // hi*hi
                        mma16816(acc[mt][nt], ah[mt], blp);   // hi*lo
                        mma16816(acc[mt][nt], al[mt], bhp);   // lo*hi
                    }
            }
        }
        __syncthreads();
        if (t + 2 < ns) CP_B(t + 2);
    }
#undef LDG_A
#undef STS_A
#undef CP_B

    // store partial G
    float* G = g_Gpart[split];
    #pragma unroll
    for (int mt = 0; mt < 2; mt++)
        #pragma unroll
        for (int nt = 0; nt < 8; nt++) {
            int j = j0 + wm * 32 + mt * 16 + (lane >> 2);
            int d = wn * 64 + nt * 8 + (lane & 3) * 2;
            if (j < NN) {
                float2 v = make_float2(acc[mt][nt][0], acc[mt][nt][1]);
                *(float2*)(G + (size_t)j * DD + d) = v;
            }
            if (j + 8 < NN) {
                float2 v = make_float2(acc[mt][nt][2], acc[mt][nt][3]);
                *(float2*)(G + (size_t)(j + 8) * DD + d) = v;
            }
        }
}

// ---------------- 5) h = tanh(dinv_j*(sum G + P_j) + b); scores ----------------
__global__ __launch_bounds__(128) void epilogue_kernel(const float* __restrict__ b_gcn,
                                                       const float* __restrict__ w_score,
                                                       const float* __restrict__ b_score,
                                                       float* __restrict__ out) {
    int j = blockIdx.x;
    int d = threadIdx.x;
    size_t o = (size_t)j * DD + d;
    float g = g_P[o];
    #pragma unroll
    for (int s = 0; s < NSPLIT; s++) g += g_Gpart[s][o];
    float hv = tanhf(g_dinv[j] * g + b_gcn[d]);
    g_h[o] = hv;
    float v = hv * w_score[d];
    #pragma unroll
    for (int off = 16; off > 0; off >>= 1) v += __shfl_down_sync(0xffffffffu, v, off);
    __shared__ float ws[4];
    if ((d & 31) == 0) ws[d >> 5] = v;
    __syncthreads();
    if (d == 0) {
        float sc = ((ws[0] + ws[1]) + (ws[2] + ws[3])) + b_score[0];
        g_scores[j] = sc;
        out[SC_OFF + j] = sc;
    }
}

// ---------------- 6) top-k via exact rank (matches lax.top_k stable ties) ----------------
__global__ __launch_bounds__(256) void topk_rank_kernel() {
    __shared__ float ss[NN];
    int tid = threadIdx.x;
    for (int f = tid; f < NN; f += 256) ss[f] = g_scores[f];
    __syncthreads();
    int j = blockIdx.x * 256 + tid;
    if (j >= NN) return;
    float sj = ss[j];
    int rank = 0;
    for (int i = 0; i < NN; i++) {
        float si = ss[i];
        rank += (si > sj) ? 1 : ((si == sj && i < j) ? 1 : 0);
    }
    g_sel[j] = (rank < KSEL) ? 1 : 0;
}

// ---------------- 7) compact selected indices (ascending) + exclusive scan ----------------
__global__ __launch_bounds__(256) void compact_kernel(float* __restrict__ out) {
    __shared__ int wsum[8];
    __shared__ int carry;
    int tid = threadIdx.x, lane = tid & 31, wid = tid >> 5;
    if (tid == 0) carry = 0;
    __syncthreads();
    for (int base = 0; base < NN; base += 256) {
        int j = base + tid;
        int f = (j < NN) ? g_sel[j] : 0;
        int xv = f;
        #pragma unroll
        for (int o = 1; o < 32; o <<= 1) {
            int y = __shfl_up_sync(0xffffffffu, xv, o);
            if (lane >= o) xv += y;
        }
        if (lane == 31) wsum[wid] = xv;
        __syncthreads();
        int woff = 0;
        #pragma unroll
        for (int w = 0; w < 8; w++) if (w < wid) woff += wsum[w];
        int incl = xv + woff;
        int pos = carry + incl - f;
        if (j < NN) {
            g_epos[j] = pos;
            if (f) {
                g_idx[pos] = j;
                out[IDX_OFF + pos] = (float)j;
            }
        }
        __syncthreads();
        if (tid == 255) carry += incl;
        __syncthreads();
    }
}

// ---------------- 8) x_pool gather ----------------
__global__ __launch_bounds__(128) void gather_x_kernel(float* __restrict__ out) {
    int r = blockIdx.x;
    int d = threadIdx.x;
    int ir = g_idx[r];
    out[XP_OFF + (size_t)r * DD + d] = g_h[(size_t)ir * DD + d];
}

// ---------------- 9) adjacency/motif pool gathers (smem-staged, coalesced DRAM reads) ----------------
__global__ __launch_bounds__(256) void gather_pools_kernel(const float* __restrict__ adj,
                                                           const float* __restrict__ motif,
                                                           float* __restrict__ out) {
    __shared__ float smA[CI];
    __shared__ float smM[CI];
    __shared__ int scr[2];
    int tid = threadIdx.x;
    int r = blockIdx.x;
    int ir = g_idx[r];
    const float* arow = adj   + (size_t)ir * NN;
    const float* mrow = motif + (size_t)ir * NN;
    float* oa = out + ADJ_OFF + (size_t)r * KSEL;
    float* om = out + MOT_OFF + (size_t)r * KSEL;

    for (int q0 = 0; q0 < NN; q0 += CI) {
        int qn = min(CI, NN - q0);
        for (int f = tid * 4; f < qn; f += 1024) {
            *(float4*)&smA[f] = *(const float4*)&arow[q0 + f];
            *(float4*)&smM[f] = *(const float4*)&mrow[q0 + f];
        }
        if (tid == 0) {
            scr[0] = g_epos[q0];
            scr[1] = (q0 + CI < NN) ? g_epos[q0 + CI] : KSEL;
        }
        __syncthreads();
        int c0 = scr[0], c1 = scr[1];
        for (int c = c0 + tid; c < c1; c += 256) {
            int ic = g_idx[c] - q0;
            oa[c] = smA[ic];
            om[c] = smM[ic];
        }
        __syncthreads();
    }
}

// ---------------- launch ----------------
extern "C" void kernel_launch(void* const* d_in, const int* in_sizes, int n_in,
                              void* d_out, int out_size) {
    const float* x       = (const float*)d_in[0];
    const float* adj     = (const float*)d_in[1];
    const float* motif   = (const float*)d_in[2];
    const float* W       = (const float*)d_in[3];
    const float* b_gcn   = (const float*)d_in[4];
    const float* w_score = (const float*)d_in[5];
    const float* b_score = (const float*)d_in[6];
    float* out = (float*)d_out;

    cudaFuncSetAttribute(hmma_gemm_kernel, cudaFuncAttributeMaxDynamicSharedMemorySize, 65536);

    colsum_kernel<<<dim3((NN + 255) / 256, NPART), 256>>>(motif);
    dinv_kernel<<<(NN + 255) / 256, 256>>>();
    compute_P_kernel<<<NN / 16, 128>>>(x, W);
    hmma_gemm_kernel<<<dim3(NJT, NSPLIT), 256, 65536>>>(motif);
    epilogue_kernel<<<NN, 128>>>(b_gcn, w_score, b_score, out);
    topk_rank_kernel<<<(NN + 255) / 256, 256>>>();
    compact_kernel<<<1, 256>>>(out);
    gather_x_kernel<<<KSEL, 128>>>(out);
    gather_pools_kernel<<<KSEL, 256>>>(adj, motif, out);
}